// round 6
// baseline (speedup 1.0000x reference)
#include <cuda_runtime.h>
#include <cuda_bf16.h>
#include <math.h>
#include <stdint.h>

// ---------------------------------------------------------------------------
// Problem constants (fixed by setup_inputs)
// ---------------------------------------------------------------------------
#define BATCH   4
#define SEQ     1024          // 32*32 grid
#define EMB     512
#define HEADS   8
#define HDIM    64            // EMB / HEADS
#define LAYERS  4
#define MROWS   (BATCH * SEQ) // 4096
#define GRID_W  32            // sqrt(SEQ)

// ---------------------------------------------------------------------------
// Scratch (device globals; no allocation allowed)
// ---------------------------------------------------------------------------
__device__ float g_h   [MROWS * EMB];
__device__ float g_ln  [MROWS * EMB];
__device__ float g_qkv [MROWS * 3 * EMB];
__device__ float g_att [MROWS * EMB];
__device__ float g_ff  [MROWS * EMB];
__device__ float g_mid [MROWS * 4 * EMB];

// ---------------------------------------------------------------------------
// GELU (exact, erf-based — matches jax.nn.gelu(approximate=False))
// ---------------------------------------------------------------------------
__device__ __forceinline__ float gelu_exact(float x) {
    return 0.5f * x * (1.0f + erff(x * 0.70710678118654752440f));
}

// ---------------------------------------------------------------------------
// Tensor-core primitives (TF32 m16n8k8)
// ---------------------------------------------------------------------------
__device__ __forceinline__ void mma_tf32(float* d, const uint32_t* a, const uint32_t* b) {
    asm volatile(
        "mma.sync.aligned.m16n8k8.row.col.f32.tf32.tf32.f32 "
        "{%0,%1,%2,%3}, {%4,%5,%6,%7}, {%8,%9}, {%0,%1,%2,%3};\n"
        : "+f"(d[0]), "+f"(d[1]), "+f"(d[2]), "+f"(d[3])
        : "r"(a[0]), "r"(a[1]), "r"(a[2]), "r"(a[3]), "r"(b[0]), "r"(b[1]));
}

__device__ __forceinline__ void ldm_x4(uint32_t* f, const float* p) {
    uint32_t s = (uint32_t)__cvta_generic_to_shared((void*)p);
    asm volatile("ldmatrix.sync.aligned.m8n8.x4.shared.b16 {%0,%1,%2,%3}, [%4];\n"
        : "=r"(f[0]), "=r"(f[1]), "=r"(f[2]), "=r"(f[3]) : "r"(s));
}

__device__ __forceinline__ void cp_async16(uint32_t saddr, const void* gptr) {
    asm volatile("cp.async.cg.shared.global [%0], [%1], 16;\n" :: "r"(saddr), "l"(gptr));
}
__device__ __forceinline__ void cp_commit() {
    asm volatile("cp.async.commit_group;\n");
}
template<int N>
__device__ __forceinline__ void cp_wait() {
    asm volatile("cp.async.wait_group %0;\n" :: "n"(N));
}

// ---------------------------------------------------------------------------
// TF32 tensor-core GEMM: C[M,N] = epi( A[M,K] @ W[N,K]^T + bias[N] [+res] )
// CTA tile 128x128, BK=16, 3-stage cp.async pipeline, 256 thr = 8 warps,
// warp tile 64x32. Smem rows padded to 20 floats (80B: 16B-aligned for
// cp.async, conflict-free ldmatrix phases). Dynamic smem = 3 * 20480 B.
// Requires M%128==0, N%128==0, K%16==0.
// ---------------------------------------------------------------------------
#define SM_STRIDE 20
#define STAGE_FLOATS (2 * 128 * SM_STRIDE)   // A(2560) + B(2560) = 5120 floats
#define STAGE_BYTES  (STAGE_FLOATS * 4)      // 20480
#define GEMM_SMEM    (3 * STAGE_BYTES)       // 61440

template<int ACT, bool RES>
__global__ __launch_bounds__(256, 1)
void tgemm_kernel(const float* __restrict__ A,
                  const float* __restrict__ W,
                  const float* __restrict__ bias,
                  const float* __restrict__ res,
                  float* __restrict__ C,
                  int M, int N, int K)
{
    extern __shared__ float smem[];

    const int bm   = blockIdx.y * 128;
    const int bn   = blockIdx.x * 128;
    const int tid  = threadIdx.x;
    const int warp = tid >> 5;
    const int lane = tid & 31;
    const int wm   = (warp >> 2) * 64;
    const int wn   = (warp & 3) * 32;

    // ---- gmem -> smem mapping: 2 threads per row, 8 floats each (2x16B) ----
    const int r0 = tid >> 1;             // row 0..127
    const int kq = (tid & 1) * 8;        // float offset within 16-float k-slab
    const float* Ag = A + (size_t)(bm + r0) * K + kq;
    const float* Wg = W + (size_t)(bn + r0) * K + kq;

    const uint32_t sbase = (uint32_t)__cvta_generic_to_shared((void*)smem);
    const uint32_t aoff  = (uint32_t)(r0 * SM_STRIDE + kq) * 4;          // bytes
    const uint32_t boff  = (uint32_t)(128 * SM_STRIDE * 4) + aoff;

    // ---- ldmatrix per-lane source offsets ----
    const int lg   = lane >> 3;
    const int lr   = lane & 7;
    const int lrow = (lg & 1) * 8 + lr;
    const int lcol = (lg >> 1) * 4;

    float acc[4][4][4];
    #pragma unroll
    for (int mt = 0; mt < 4; mt++)
        #pragma unroll
        for (int nt = 0; nt < 4; nt++)
            #pragma unroll
            for (int i = 0; i < 4; i++) acc[mt][nt][i] = 0.0f;

    const int nk = K >> 4;

    // ---- prologue: stages 0,1 in flight ----
    #pragma unroll
    for (int s = 0; s < 2; s++) {
        const float* a = Ag + (size_t)s * 16;
        const float* w = Wg + (size_t)s * 16;
        const uint32_t base = sbase + s * STAGE_BYTES;
        cp_async16(base + aoff,      a);
        cp_async16(base + aoff + 16, a + 4);
        cp_async16(base + boff,      w);
        cp_async16(base + boff + 16, w + 4);
        cp_commit();
    }

    int s_cur = 0, s_nxt = 2;
    for (int kt = 0; kt < nk; kt++) {
        cp_wait<1>();
        __syncthreads();

        // issue load for kt+2 into the stage consumed at kt-1 (sync above
        // guarantees all warps are done reading it)
        if (kt + 2 < nk) {
            const float* a = Ag + (size_t)(kt + 2) * 16;
            const float* w = Wg + (size_t)(kt + 2) * 16;
            const uint32_t base = sbase + s_nxt * STAGE_BYTES;
            cp_async16(base + aoff,      a);
            cp_async16(base + aoff + 16, a + 4);
            cp_async16(base + boff,      w);
            cp_async16(base + boff + 16, w + 4);
        }
        cp_commit();   // empty groups at the tail keep wait_group counts valid

        const float* Ac = smem + s_cur * STAGE_FLOATS;
        const float* Bc = Ac + 128 * SM_STRIDE;

        #pragma unroll
        for (int ks = 0; ks < 2; ks++) {
            uint32_t afr[4][4];
            uint32_t bfr[4][2];
            #pragma unroll
            for (int mt = 0; mt < 4; mt++)
                ldm_x4(afr[mt], &Ac[(wm + mt * 16 + lrow) * SM_STRIDE + ks * 8 + lcol]);
            #pragma unroll
            for (int j = 0; j < 2; j++) {
                uint32_t t[4];
                ldm_x4(t, &Bc[(wn + j * 16 + lrow) * SM_STRIDE + ks * 8 + lcol]);
                bfr[2 * j][0]     = t[0];
                bfr[2 * j + 1][0] = t[1];
                bfr[2 * j][1]     = t[2];
                bfr[2 * j + 1][1] = t[3];
            }
            #pragma unroll
            for (int mt = 0; mt < 4; mt++)
                #pragma unroll
                for (int nt = 0; nt < 4; nt++)
                    mma_tf32(acc[mt][nt], afr[mt], bfr[nt]);
        }

        s_cur = (s_cur + 1 == 3) ? 0 : s_cur + 1;
        s_nxt = (s_nxt + 1 == 3) ? 0 : s_nxt + 1;
    }

    // ---- epilogue: bias (+gelu) (+res), float2 stores ----
    const int g  = lane >> 2;
    const int cc = (lane & 3) * 2;
    #pragma unroll
    for (int mt = 0; mt < 4; mt++) {
        const int row = bm + wm + mt * 16 + g;   // and row+8
        #pragma unroll
        for (int nt = 0; nt < 4; nt++) {
            const int col = bn + wn + nt * 8 + cc;
            const float2 bv = *(const float2*)&bias[col];
            float v0 = acc[mt][nt][0] + bv.x;
            float v1 = acc[mt][nt][1] + bv.y;
            float v2 = acc[mt][nt][2] + bv.x;
            float v3 = acc[mt][nt][3] + bv.y;
            if (ACT == 1) {
                v0 = gelu_exact(v0); v1 = gelu_exact(v1);
                v2 = gelu_exact(v2); v3 = gelu_exact(v3);
            }
            if (RES) {
                const float2 ra = *(const float2*)&res[(size_t)row * N + col];
                const float2 rb = *(const float2*)&res[(size_t)(row + 8) * N + col];
                v0 += ra.x; v1 += ra.y; v2 += rb.x; v3 += rb.y;
            }
            float2 o0 = {v0, v1};
            float2 o1 = {v2, v3};
            *(float2*)&C[(size_t)row * N + col]       = o0;
            *(float2*)&C[(size_t)(row + 8) * N + col] = o1;
        }
    }
}

// ---------------------------------------------------------------------------
// LayerNorm over last dim (E=512). One block (128 threads, float4) per row.
// ---------------------------------------------------------------------------
__global__ void ln_kernel(const float* __restrict__ x,
                          const float* __restrict__ g,
                          const float* __restrict__ b,
                          float* __restrict__ y)
{
    const int row = blockIdx.x;
    const int t   = threadIdx.x;  // 0..127
    const float4 v = ((const float4*)(x + (size_t)row * EMB))[t];

    float s  = v.x + v.y + v.z + v.w;
    float ss = v.x * v.x + v.y * v.y + v.z * v.z + v.w * v.w;
    #pragma unroll
    for (int o = 16; o; o >>= 1) {
        s  += __shfl_xor_sync(0xffffffffu, s,  o);
        ss += __shfl_xor_sync(0xffffffffu, ss, o);
    }
    __shared__ float sm[4], sm2[4];
    if ((t & 31) == 0) { sm[t >> 5] = s; sm2[t >> 5] = ss; }
    __syncthreads();
    s  = sm[0]  + sm[1]  + sm[2]  + sm[3];
    ss = sm2[0] + sm2[1] + sm2[2] + sm2[3];

    const float mean = s * (1.0f / EMB);
    const float var  = ss * (1.0f / EMB) - mean * mean;
    const float inv  = rsqrtf(var + 1e-5f);

    const float4 gg = ((const float4*)g)[t];
    const float4 bb = ((const float4*)b)[t];
    float4 o;
    o.x = (v.x - mean) * inv * gg.x + bb.x;
    o.y = (v.y - mean) * inv * gg.y + bb.y;
    o.z = (v.z - mean) * inv * gg.z + bb.z;
    o.w = (v.w - mean) * inv * gg.w + bb.w;
    ((float4*)(y + (size_t)row * EMB))[t] = o;
}

// ---------------------------------------------------------------------------
// Windowed attention. One warp per (batch, head, query); <=9 unmasked keys.
// qkv layout: [MROWS, 3*EMB] = [q | k | v], head h at column h*64.
// ---------------------------------------------------------------------------
__global__ void attn_kernel(const float* __restrict__ qkv,
                            float* __restrict__ out)
{
    const int gw   = blockIdx.x * 8 + (threadIdx.x >> 5);
    const int lane = threadIdx.x & 31;

    const int qpos = gw & (SEQ - 1);
    const int h    = (gw >> 10) & (HEADS - 1);
    const int b    = gw >> 13;

    const int row = b * SEQ + qpos;
    const float* qp = qkv + (size_t)row * (3 * EMB) + h * HDIM;
    const float q0 = qp[lane]      * 0.125f;   // 1/sqrt(64)
    const float q1 = qp[lane + 32] * 0.125f;

    const int y = qpos >> 5;
    const int x = qpos & 31;

    float s[9];
    int   krow[9];
    int   n = 0;
    #pragma unroll
    for (int dy = -1; dy <= 1; dy++) {
        #pragma unroll
        for (int dx = -1; dx <= 1; dx++) {
            const int ny = y + dy, nx = x + dx;
            if (ny < 0 || ny >= GRID_W || nx < 0 || nx >= GRID_W) continue;
            const int kr = b * SEQ + (ny << 5) + nx;
            const float* kp = qkv + (size_t)kr * (3 * EMB) + EMB + h * HDIM;
            float p = q0 * kp[lane] + q1 * kp[lane + 32];
            #pragma unroll
            for (int o = 16; o; o >>= 1) p += __shfl_xor_sync(0xffffffffu, p, o);
            s[n] = p; krow[n] = kr; n++;
        }
    }

    float mx = s[0];
    for (int j = 1; j < n; j++) mx = fmaxf(mx, s[j]);
    float sum = 0.0f;
    for (int j = 0; j < n; j++) { s[j] = expf(s[j] - mx); sum += s[j]; }
    const float inv = 1.0f / sum;

    float o0 = 0.0f, o1 = 0.0f;
    for (int j = 0; j < n; j++) {
        const float* vp = qkv + (size_t)krow[j] * (3 * EMB) + 2 * EMB + h * HDIM;
        const float a = s[j] * inv;
        o0 = fmaf(a, vp[lane],      o0);
        o1 = fmaf(a, vp[lane + 32], o1);
    }
    out[(size_t)row * EMB + h * HDIM + lane]      = o0;
    out[(size_t)row * EMB + h * HDIM + lane + 32] = o1;
}

// ---------------------------------------------------------------------------
// Elementwise helper
// ---------------------------------------------------------------------------
__global__ void add_kernel(const float* __restrict__ a, const float* __restrict__ b,
                           float* __restrict__ dst, int n4) {
    int i = blockIdx.x * blockDim.x + threadIdx.x;
    if (i < n4) {
        float4 va = ((const float4*)a)[i];
        float4 vb = ((const float4*)b)[i];
        float4 o = {va.x + vb.x, va.y + vb.y, va.z + vb.z, va.w + vb.w};
        ((float4*)dst)[i] = o;
    }
}

// ---------------------------------------------------------------------------
// Host orchestration
// ---------------------------------------------------------------------------
static inline void run_gemm(int act, bool res_flag,
                            const float* A, const float* W, const float* bias,
                            const float* res, float* C, int M, int N, int K,
                            cudaStream_t s)
{
    dim3 grid(N / 128, M / 128);
    if (act == 0 && !res_flag)      tgemm_kernel<0, false><<<grid, 256, GEMM_SMEM, s>>>(A, W, bias, res, C, M, N, K);
    else if (act == 0 && res_flag)  tgemm_kernel<0, true ><<<grid, 256, GEMM_SMEM, s>>>(A, W, bias, res, C, M, N, K);
    else if (act == 1 && !res_flag) tgemm_kernel<1, false><<<grid, 256, GEMM_SMEM, s>>>(A, W, bias, res, C, M, N, K);
    else                            tgemm_kernel<1, true ><<<grid, 256, GEMM_SMEM, s>>>(A, W, bias, res, C, M, N, K);
}

extern "C" void kernel_launch(void* const* d_in, const int* in_sizes, int n_in,
                              void* d_out, int out_size)
{
    (void)in_sizes; (void)n_in; (void)out_size;
    const float* x      = (const float*)d_in[0];
    // d_in[1] = mask : structure exploited analytically (3x3 window, 32x32 grid)
    const float* in_w   = (const float*)d_in[2];
    const float* in_b   = (const float*)d_in[3];
    const float* out_w  = (const float*)d_in[4];
    const float* out_b  = (const float*)d_in[5];
    const float* ln1_g  = (const float*)d_in[6];
    const float* ln1_b  = (const float*)d_in[7];
    const float* ln2_g  = (const float*)d_in[8];
    const float* ln2_b  = (const float*)d_in[9];
    const float* ff1_w  = (const float*)d_in[10];
    const float* ff1_b  = (const float*)d_in[11];
    const float* ff2_w  = (const float*)d_in[12];
    const float* ff2_b  = (const float*)d_in[13];
    const float* mlp_ln_g = (const float*)d_in[14];
    const float* mlp_ln_b = (const float*)d_in[15];
    const float* mlp_w1 = (const float*)d_in[16];
    const float* mlp_b1 = (const float*)d_in[17];
    const float* mlp_w2 = (const float*)d_in[18];
    const float* mlp_b2 = (const float*)d_in[19];
    float* out = (float*)d_out;

    // opt-in to >48KB dynamic smem (idempotent; host-side, not captured)
    cudaFuncSetAttribute(tgemm_kernel<0, false>, cudaFuncAttributeMaxDynamicSharedMemorySize, GEMM_SMEM);
    cudaFuncSetAttribute(tgemm_kernel<0, true >, cudaFuncAttributeMaxDynamicSharedMemorySize, GEMM_SMEM);
    cudaFuncSetAttribute(tgemm_kernel<1, false>, cudaFuncAttributeMaxDynamicSharedMemorySize, GEMM_SMEM);
    cudaFuncSetAttribute(tgemm_kernel<1, true >, cudaFuncAttributeMaxDynamicSharedMemorySize, GEMM_SMEM);

    float *h, *ln, *qkv, *att, *ff, *mid;
    cudaGetSymbolAddress((void**)&h,   g_h);
    cudaGetSymbolAddress((void**)&ln,  g_ln);
    cudaGetSymbolAddress((void**)&qkv, g_qkv);
    cudaGetSymbolAddress((void**)&att, g_att);
    cudaGetSymbolAddress((void**)&ff,  g_ff);
    cudaGetSymbolAddress((void**)&mid, g_mid);

    cudaStream_t s = 0;
    const int M = MROWS, E = EMB;
    const int n4  = M * E / 4;
    const int eb  = 256;
    const int eg  = (n4 + eb - 1) / eb;

    const float* cur = x;   // residual stream; layer 0 reads the input directly

    for (int l = 0; l < LAYERS; l++) {
        const float* iw  = in_w  + (size_t)l * 3 * E * E;
        const float* ib  = in_b  + (size_t)l * 3 * E;
        const float* ow  = out_w + (size_t)l * E * E;
        const float* ob  = out_b + (size_t)l * E;
        const float* l1g = ln1_g + (size_t)l * E;
        const float* l1b = ln1_b + (size_t)l * E;
        const float* l2g = ln2_g + (size_t)l * E;
        const float* l2b = ln2_b + (size_t)l * E;
        const float* f1w = ff1_w + (size_t)l * E * E;
        const float* f1b = ff1_b + (size_t)l * E;
        const float* f2w = ff2_w + (size_t)l * E * E;
        const float* f2b = ff2_b + (size_t)l * E;

        // h_ln = LN1(cur)
        ln_kernel<<<M, 128, 0, s>>>(cur, l1g, l1b, ln);
        // qkv = h_ln @ in_w^T + in_b
        run_gemm(0, false, ln, iw, ib, nullptr, qkv, M, 3 * E, E, s);
        // att = windowed_softmax_attention(qkv)
        attn_kernel<<<(BATCH * HEADS * SEQ) / 8, 256, 0, s>>>(qkv, att);
        // h = cur + att @ out_w^T + out_b
        run_gemm(0, true, att, ow, ob, cur, h, M, E, E, s);
        cur = h;
        // h_ln = LN2(h)
        ln_kernel<<<M, 128, 0, s>>>(h, l2g, l2b, ln);
        // ff = gelu(h_ln @ ff1_w^T + ff1_b)
        run_gemm(1, false, ln, f1w, f1b, nullptr, ff, M, E, E, s);
        // h = h + ff @ ff2_w^T + ff2_b
        run_gemm(0, true, ff, f2w, f2b, h, h, M, E, E, s);
    }

    // out = x + h
    add_kernel<<<eg, eb, 0, s>>>(x, h, out, n4);
    // ln = LN(out)
    ln_kernel<<<M, 128, 0, s>>>(out, mlp_ln_g, mlp_ln_b, ln);
    // mid = gelu(ln @ mlp_w1^T + mlp_b1)   [M, 2048]
    run_gemm(1, false, ln, mlp_w1, mlp_b1, nullptr, mid, M, 4 * E, E, s);
    // out = out + mid @ mlp_w2^T + mlp_b2
    run_gemm(0, true, mid, mlp_w2, mlp_b2, out, out, M, E, 4 * E, s);
}

// round 7
// speedup vs baseline: 1.0824x; 1.0824x over previous
#include <cuda_runtime.h>
#include <cuda_bf16.h>
#include <math.h>
#include <stdint.h>

// ---------------------------------------------------------------------------
// Problem constants (fixed by setup_inputs)
// ---------------------------------------------------------------------------
#define BATCH   4
#define SEQ     1024          // 32*32 grid
#define EMB     512
#define HEADS   8
#define HDIM    64            // EMB / HEADS
#define LAYERS  4
#define MROWS   (BATCH * SEQ) // 4096
#define GRID_W  32            // sqrt(SEQ)

// ---------------------------------------------------------------------------
// Scratch (device globals; no allocation allowed)
// ---------------------------------------------------------------------------
__device__ float g_h   [MROWS * EMB];
__device__ float g_ln  [MROWS * EMB];
__device__ float g_qkv [MROWS * 3 * EMB];
__device__ float g_att [MROWS * EMB];
__device__ float g_ff  [MROWS * EMB];
__device__ float g_mid [MROWS * 4 * EMB];

// ---------------------------------------------------------------------------
// GELU (exact, erf-based — matches jax.nn.gelu(approximate=False))
// ---------------------------------------------------------------------------
__device__ __forceinline__ float gelu_exact(float x) {
    return 0.5f * x * (1.0f + erff(x * 0.70710678118654752440f));
}

// ---------------------------------------------------------------------------
// Tensor-core primitives (TF32 m16n8k8)
// ---------------------------------------------------------------------------
__device__ __forceinline__ void mma_tf32(float* d, const uint32_t* a, const uint32_t* b) {
    asm volatile(
        "mma.sync.aligned.m16n8k8.row.col.f32.tf32.tf32.f32 "
        "{%0,%1,%2,%3}, {%4,%5,%6,%7}, {%8,%9}, {%0,%1,%2,%3};\n"
        : "+f"(d[0]), "+f"(d[1]), "+f"(d[2]), "+f"(d[3])
        : "r"(a[0]), "r"(a[1]), "r"(a[2]), "r"(a[3]), "r"(b[0]), "r"(b[1]));
}

__device__ __forceinline__ void ldm_x4(uint32_t* f, const float* p) {
    uint32_t s = (uint32_t)__cvta_generic_to_shared((void*)p);
    asm volatile("ldmatrix.sync.aligned.m8n8.x4.shared.b16 {%0,%1,%2,%3}, [%4];\n"
        : "=r"(f[0]), "=r"(f[1]), "=r"(f[2]), "=r"(f[3]) : "r"(s));
}

__device__ __forceinline__ void cp_async16(uint32_t saddr, const void* gptr) {
    asm volatile("cp.async.cg.shared.global [%0], [%1], 16;\n" :: "r"(saddr), "l"(gptr));
}
__device__ __forceinline__ void cp_commit() {
    asm volatile("cp.async.commit_group;\n");
}
template<int N>
__device__ __forceinline__ void cp_wait() {
    asm volatile("cp.async.wait_group %0;\n" :: "n"(N));
}

// ---------------------------------------------------------------------------
// TF32 tensor-core GEMM: C[M,N] = epi( A[M,K] @ W[N,K]^T + bias[N] [+res] )
// CTA tile 128x128, BK=16, 3-stage cp.async pipeline.
// 512 threads = 16 warps in a 4x4 grid, warp tile 32x32 (4 warps/SMSP for
// latency hiding — round-6 showed 2 warps/SMSP leaves issue at 20%).
// Smem rows padded to 20 floats (80B: 16B-aligned cp.async dst, conflict-free
// ldmatrix phases). Dynamic smem = 3 * 20480 B.
// Requires M%128==0, N%128==0, K%16==0.
// ---------------------------------------------------------------------------
#define SM_STRIDE 20
#define STAGE_FLOATS (2 * 128 * SM_STRIDE)   // A(2560) + B(2560) = 5120 floats
#define STAGE_BYTES  (STAGE_FLOATS * 4)      // 20480
#define GEMM_SMEM    (3 * STAGE_BYTES)       // 61440

template<int ACT, bool RES>
__global__ __launch_bounds__(512, 1)
void tgemm_kernel(const float* __restrict__ A,
                  const float* __restrict__ W,
                  const float* __restrict__ bias,
                  const float* __restrict__ res,
                  float* __restrict__ C,
                  int M, int N, int K)
{
    extern __shared__ float smem[];

    const int bm   = blockIdx.y * 128;
    const int bn   = blockIdx.x * 128;
    const int tid  = threadIdx.x;
    const int warp = tid >> 5;
    const int lane = tid & 31;
    const int wm   = (warp >> 2) * 32;   // 4 warp rows
    const int wn   = (warp & 3) * 32;    // 4 warp cols

    // ---- gmem -> smem: one cp.async16 per thread per operand ----
    const int r0 = tid >> 2;             // row 0..127
    const int kq = (tid & 3) * 4;        // float offset within 16-float k-slab
    const float* Ag = A + (size_t)(bm + r0) * K + kq;
    const float* Wg = W + (size_t)(bn + r0) * K + kq;

    const uint32_t sbase = (uint32_t)__cvta_generic_to_shared((void*)smem);
    const uint32_t aoff  = (uint32_t)(r0 * SM_STRIDE + kq) * 4;          // bytes
    const uint32_t boff  = (uint32_t)(128 * SM_STRIDE * 4) + aoff;

    // ---- ldmatrix per-lane source offsets (verified mapping, unchanged) ----
    const int lg   = lane >> 3;
    const int lr   = lane & 7;
    const int lrow = (lg & 1) * 8 + lr;
    const int lcol = (lg >> 1) * 4;

    float acc[2][4][4];
    #pragma unroll
    for (int mt = 0; mt < 2; mt++)
        #pragma unroll
        for (int nt = 0; nt < 4; nt++)
            #pragma unroll
            for (int i = 0; i < 4; i++) acc[mt][nt][i] = 0.0f;

    const int nk = K >> 4;

    // ---- prologue: stages 0,1 in flight ----
    #pragma unroll
    for (int s = 0; s < 2; s++) {
        const float* a = Ag + (size_t)s * 16;
        const float* w = Wg + (size_t)s * 16;
        const uint32_t base = sbase + s * STAGE_BYTES;
        cp_async16(base + aoff, a);
        cp_async16(base + boff, w);
        cp_commit();
    }

    int s_cur = 0, s_nxt = 2;
    for (int kt = 0; kt < nk; kt++) {
        cp_wait<1>();
        __syncthreads();

        if (kt + 2 < nk) {
            const float* a = Ag + (size_t)(kt + 2) * 16;
            const float* w = Wg + (size_t)(kt + 2) * 16;
            const uint32_t base = sbase + s_nxt * STAGE_BYTES;
            cp_async16(base + aoff, a);
            cp_async16(base + boff, w);
        }
        cp_commit();   // empty groups at the tail keep wait_group counts valid

        const float* Ac = smem + s_cur * STAGE_FLOATS;
        const float* Bc = Ac + 128 * SM_STRIDE;

        #pragma unroll
        for (int ks = 0; ks < 2; ks++) {
            uint32_t afr[2][4];
            uint32_t bfr[4][2];
            #pragma unroll
            for (int mt = 0; mt < 2; mt++)
                ldm_x4(afr[mt], &Ac[(wm + mt * 16 + lrow) * SM_STRIDE + ks * 8 + lcol]);
            #pragma unroll
            for (int j = 0; j < 2; j++) {
                uint32_t t[4];
                ldm_x4(t, &Bc[(wn + j * 16 + lrow) * SM_STRIDE + ks * 8 + lcol]);
                bfr[2 * j][0]     = t[0];
                bfr[2 * j + 1][0] = t[1];
                bfr[2 * j][1]     = t[2];
                bfr[2 * j + 1][1] = t[3];
            }
            #pragma unroll
            for (int mt = 0; mt < 2; mt++)
                #pragma unroll
                for (int nt = 0; nt < 4; nt++)
                    mma_tf32(acc[mt][nt], afr[mt], bfr[nt]);
        }

        s_cur = (s_cur + 1 == 3) ? 0 : s_cur + 1;
        s_nxt = (s_nxt + 1 == 3) ? 0 : s_nxt + 1;
    }

    // ---- epilogue: bias (+gelu) (+res), float2 stores ----
    const int g  = lane >> 2;
    const int cc = (lane & 3) * 2;
    #pragma unroll
    for (int mt = 0; mt < 2; mt++) {
        const int row = bm + wm + mt * 16 + g;   // and row+8
        #pragma unroll
        for (int nt = 0; nt < 4; nt++) {
            const int col = bn + wn + nt * 8 + cc;
            const float2 bv = *(const float2*)&bias[col];
            float v0 = acc[mt][nt][0] + bv.x;
            float v1 = acc[mt][nt][1] + bv.y;
            float v2 = acc[mt][nt][2] + bv.x;
            float v3 = acc[mt][nt][3] + bv.y;
            if (ACT == 1) {
                v0 = gelu_exact(v0); v1 = gelu_exact(v1);
                v2 = gelu_exact(v2); v3 = gelu_exact(v3);
            }
            if (RES) {
                const float2 ra = *(const float2*)&res[(size_t)row * N + col];
                const float2 rb = *(const float2*)&res[(size_t)(row + 8) * N + col];
                v0 += ra.x; v1 += ra.y; v2 += rb.x; v3 += rb.y;
            }
            float2 o0 = {v0, v1};
            float2 o1 = {v2, v3};
            *(float2*)&C[(size_t)row * N + col]       = o0;
            *(float2*)&C[(size_t)(row + 8) * N + col] = o1;
        }
    }
}

// ---------------------------------------------------------------------------
// LayerNorm over last dim (E=512). One block (128 threads, float4) per row.
// ---------------------------------------------------------------------------
__global__ void ln_kernel(const float* __restrict__ x,
                          const float* __restrict__ g,
                          const float* __restrict__ b,
                          float* __restrict__ y)
{
    const int row = blockIdx.x;
    const int t   = threadIdx.x;  // 0..127
    const float4 v = ((const float4*)(x + (size_t)row * EMB))[t];

    float s  = v.x + v.y + v.z + v.w;
    float ss = v.x * v.x + v.y * v.y + v.z * v.z + v.w * v.w;
    #pragma unroll
    for (int o = 16; o; o >>= 1) {
        s  += __shfl_xor_sync(0xffffffffu, s,  o);
        ss += __shfl_xor_sync(0xffffffffu, ss, o);
    }
    __shared__ float sm[4], sm2[4];
    if ((t & 31) == 0) { sm[t >> 5] = s; sm2[t >> 5] = ss; }
    __syncthreads();
    s  = sm[0]  + sm[1]  + sm[2]  + sm[3];
    ss = sm2[0] + sm2[1] + sm2[2] + sm2[3];

    const float mean = s * (1.0f / EMB);
    const float var  = ss * (1.0f / EMB) - mean * mean;
    const float inv  = rsqrtf(var + 1e-5f);

    const float4 gg = ((const float4*)g)[t];
    const float4 bb = ((const float4*)b)[t];
    float4 o;
    o.x = (v.x - mean) * inv * gg.x + bb.x;
    o.y = (v.y - mean) * inv * gg.y + bb.y;
    o.z = (v.z - mean) * inv * gg.z + bb.z;
    o.w = (v.w - mean) * inv * gg.w + bb.w;
    ((float4*)(y + (size_t)row * EMB))[t] = o;
}

// ---------------------------------------------------------------------------
// Windowed attention. One warp per (batch, head, query); <=9 unmasked keys.
// qkv layout: [MROWS, 3*EMB] = [q | k | v], head h at column h*64.
// ---------------------------------------------------------------------------
__global__ void attn_kernel(const float* __restrict__ qkv,
                            float* __restrict__ out)
{
    const int gw   = blockIdx.x * 8 + (threadIdx.x >> 5);
    const int lane = threadIdx.x & 31;

    const int qpos = gw & (SEQ - 1);
    const int h    = (gw >> 10) & (HEADS - 1);
    const int b    = gw >> 13;

    const int row = b * SEQ + qpos;
    const float* qp = qkv + (size_t)row * (3 * EMB) + h * HDIM;
    const float q0 = qp[lane]      * 0.125f;   // 1/sqrt(64)
    const float q1 = qp[lane + 32] * 0.125f;

    const int y = qpos >> 5;
    const int x = qpos & 31;

    float s[9];
    int   krow[9];
    int   n = 0;
    #pragma unroll
    for (int dy = -1; dy <= 1; dy++) {
        #pragma unroll
        for (int dx = -1; dx <= 1; dx++) {
            const int ny = y + dy, nx = x + dx;
            if (ny < 0 || ny >= GRID_W || nx < 0 || nx >= GRID_W) continue;
            const int kr = b * SEQ + (ny << 5) + nx;
            const float* kp = qkv + (size_t)kr * (3 * EMB) + EMB + h * HDIM;
            float p = q0 * kp[lane] + q1 * kp[lane + 32];
            #pragma unroll
            for (int o = 16; o; o >>= 1) p += __shfl_xor_sync(0xffffffffu, p, o);
            s[n] = p; krow[n] = kr; n++;
        }
    }

    float mx = s[0];
    for (int j = 1; j < n; j++) mx = fmaxf(mx, s[j]);
    float sum = 0.0f;
    for (int j = 0; j < n; j++) { s[j] = expf(s[j] - mx); sum += s[j]; }
    const float inv = 1.0f / sum;

    float o0 = 0.0f, o1 = 0.0f;
    for (int j = 0; j < n; j++) {
        const float* vp = qkv + (size_t)krow[j] * (3 * EMB) + 2 * EMB + h * HDIM;
        const float a = s[j] * inv;
        o0 = fmaf(a, vp[lane],      o0);
        o1 = fmaf(a, vp[lane + 32], o1);
    }
    out[(size_t)row * EMB + h * HDIM + lane]      = o0;
    out[(size_t)row * EMB + h * HDIM + lane + 32] = o1;
}

// ---------------------------------------------------------------------------
// Elementwise helper
// ---------------------------------------------------------------------------
__global__ void add_kernel(const float* __restrict__ a, const float* __restrict__ b,
                           float* __restrict__ dst, int n4) {
    int i = blockIdx.x * blockDim.x + threadIdx.x;
    if (i < n4) {
        float4 va = ((const float4*)a)[i];
        float4 vb = ((const float4*)b)[i];
        float4 o = {va.x + vb.x, va.y + vb.y, va.z + vb.z, va.w + vb.w};
        ((float4*)dst)[i] = o;
    }
}

// ---------------------------------------------------------------------------
// Host orchestration
// ---------------------------------------------------------------------------
static inline void run_gemm(int act, bool res_flag,
                            const float* A, const float* W, const float* bias,
                            const float* res, float* C, int M, int N, int K,
                            cudaStream_t s)
{
    dim3 grid(N / 128, M / 128);
    if (act == 0 && !res_flag)      tgemm_kernel<0, false><<<grid, 512, GEMM_SMEM, s>>>(A, W, bias, res, C, M, N, K);
    else if (act == 0 && res_flag)  tgemm_kernel<0, true ><<<grid, 512, GEMM_SMEM, s>>>(A, W, bias, res, C, M, N, K);
    else if (act == 1 && !res_flag) tgemm_kernel<1, false><<<grid, 512, GEMM_SMEM, s>>>(A, W, bias, res, C, M, N, K);
    else                            tgemm_kernel<1, true ><<<grid, 512, GEMM_SMEM, s>>>(A, W, bias, res, C, M, N, K);
}

extern "C" void kernel_launch(void* const* d_in, const int* in_sizes, int n_in,
                              void* d_out, int out_size)
{
    (void)in_sizes; (void)n_in; (void)out_size;
    const float* x      = (const float*)d_in[0];
    // d_in[1] = mask : structure exploited analytically (3x3 window, 32x32 grid)
    const float* in_w   = (const float*)d_in[2];
    const float* in_b   = (const float*)d_in[3];
    const float* out_w  = (const float*)d_in[4];
    const float* out_b  = (const float*)d_in[5];
    const float* ln1_g  = (const float*)d_in[6];
    const float* ln1_b  = (const float*)d_in[7];
    const float* ln2_g  = (const float*)d_in[8];
    const float* ln2_b  = (const float*)d_in[9];
    const float* ff1_w  = (const float*)d_in[10];
    const float* ff1_b  = (const float*)d_in[11];
    const float* ff2_w  = (const float*)d_in[12];
    const float* ff2_b  = (const float*)d_in[13];
    const float* mlp_ln_g = (const float*)d_in[14];
    const float* mlp_ln_b = (const float*)d_in[15];
    const float* mlp_w1 = (const float*)d_in[16];
    const float* mlp_b1 = (const float*)d_in[17];
    const float* mlp_w2 = (const float*)d_in[18];
    const float* mlp_b2 = (const float*)d_in[19];
    float* out = (float*)d_out;

    // opt-in to >48KB dynamic smem (host-side, idempotent, not captured)
    cudaFuncSetAttribute(tgemm_kernel<0, false>, cudaFuncAttributeMaxDynamicSharedMemorySize, GEMM_SMEM);
    cudaFuncSetAttribute(tgemm_kernel<0, true >, cudaFuncAttributeMaxDynamicSharedMemorySize, GEMM_SMEM);
    cudaFuncSetAttribute(tgemm_kernel<1, false>, cudaFuncAttributeMaxDynamicSharedMemorySize, GEMM_SMEM);
    cudaFuncSetAttribute(tgemm_kernel<1, true >, cudaFuncAttributeMaxDynamicSharedMemorySize, GEMM_SMEM);

    float *h, *ln, *qkv, *att, *ff, *mid;
    cudaGetSymbolAddress((void**)&h,   g_h);
    cudaGetSymbolAddress((void**)&ln,  g_ln);
    cudaGetSymbolAddress((void**)&qkv, g_qkv);
    cudaGetSymbolAddress((void**)&att, g_att);
    cudaGetSymbolAddress((void**)&ff,  g_ff);
    cudaGetSymbolAddress((void**)&mid, g_mid);

    cudaStream_t s = 0;
    const int M = MROWS, E = EMB;
    const int n4  = M * E / 4;
    const int eb  = 256;
    const int eg  = (n4 + eb - 1) / eb;

    const float* cur = x;   // residual stream; layer 0 reads the input directly

    for (int l = 0; l < LAYERS; l++) {
        const float* iw  = in_w  + (size_t)l * 3 * E * E;
        const float* ib  = in_b  + (size_t)l * 3 * E;
        const float* ow  = out_w + (size_t)l * E * E;
        const float* ob  = out_b + (size_t)l * E;
        const float* l1g = ln1_g + (size_t)l * E;
        const float* l1b = ln1_b + (size_t)l * E;
        const float* l2g = ln2_g + (size_t)l * E;
        const float* l2b = ln2_b + (size_t)l * E;
        const float* f1w = ff1_w + (size_t)l * E * E;
        const float* f1b = ff1_b + (size_t)l * E;
        const float* f2w = ff2_w + (size_t)l * E * E;
        const float* f2b = ff2_b + (size_t)l * E;

        // h_ln = LN1(cur)
        ln_kernel<<<M, 128, 0, s>>>(cur, l1g, l1b, ln);
        // qkv = h_ln @ in_w^T + in_b
        run_gemm(0, false, ln, iw, ib, nullptr, qkv, M, 3 * E, E, s);
        // att = windowed_softmax_attention(qkv)
        attn_kernel<<<(BATCH * HEADS * SEQ) / 8, 256, 0, s>>>(qkv, att);
        // h = cur + att @ out_w^T + out_b
        run_gemm(0, true, att, ow, ob, cur, h, M, E, E, s);
        cur = h;
        // h_ln = LN2(h)
        ln_kernel<<<M, 128, 0, s>>>(h, l2g, l2b, ln);
        // ff = gelu(h_ln @ ff1_w^T + ff1_b)
        run_gemm(1, false, ln, f1w, f1b, nullptr, ff, M, E, E, s);
        // h = h + ff @ ff2_w^T + ff2_b
        run_gemm(0, true, ff, f2w, f2b, h, h, M, E, E, s);
    }

    // out = x + h
    add_kernel<<<eg, eb, 0, s>>>(x, h, out, n4);
    // ln = LN(out)
    ln_kernel<<<M, 128, 0, s>>>(out, mlp_ln_g, mlp_ln_b, ln);
    // mid = gelu(ln @ mlp_w1^T + mlp_b1)   [M, 2048]
    run_gemm(1, false, ln, mlp_w1, mlp_b1, nullptr, mid, M, 4 * E, E, s);
    // out = out + mid @ mlp_w2^T + mlp_b2
    run_gemm(0, true, mid, mlp_w2, mlp_b2, out, out, M, E, 4 * E, s);
}

// round 8
// speedup vs baseline: 1.1033x; 1.0193x over previous
#include <cuda_runtime.h>
#include <cuda_bf16.h>
#include <math.h>
#include <stdint.h>

// ---------------------------------------------------------------------------
// Problem constants (fixed by setup_inputs)
// ---------------------------------------------------------------------------
#define BATCH   4
#define SEQ     1024          // 32*32 grid
#define EMB     512
#define HEADS   8
#define HDIM    64            // EMB / HEADS
#define LAYERS  4
#define MROWS   (BATCH * SEQ) // 4096
#define GRID_W  32            // sqrt(SEQ)

// ---------------------------------------------------------------------------
// Scratch (device globals; no allocation allowed)
// ---------------------------------------------------------------------------
__device__ float g_h   [MROWS * EMB];
__device__ float g_ln  [MROWS * EMB];
__device__ float g_qkv [MROWS * 3 * EMB];
__device__ float g_att [MROWS * EMB];
__device__ float g_ff  [MROWS * EMB];
__device__ float g_mid [MROWS * 4 * EMB];

// ---------------------------------------------------------------------------
// GELU (exact, erf-based — matches jax.nn.gelu(approximate=False))
// ---------------------------------------------------------------------------
__device__ __forceinline__ float gelu_exact(float x) {
    return 0.5f * x * (1.0f + erff(x * 0.70710678118654752440f));
}

// ---------------------------------------------------------------------------
// Tensor-core primitives (TF32 m16n8k8)
// ---------------------------------------------------------------------------
__device__ __forceinline__ void mma_tf32(float* d, const uint32_t* a, const uint32_t* b) {
    asm volatile(
        "mma.sync.aligned.m16n8k8.row.col.f32.tf32.tf32.f32 "
        "{%0,%1,%2,%3}, {%4,%5,%6,%7}, {%8,%9}, {%0,%1,%2,%3};\n"
        : "+f"(d[0]), "+f"(d[1]), "+f"(d[2]), "+f"(d[3])
        : "r"(a[0]), "r"(a[1]), "r"(a[2]), "r"(a[3]), "r"(b[0]), "r"(b[1]));
}

__device__ __forceinline__ void ldm_x4(uint32_t* f, const float* p) {
    uint32_t s = (uint32_t)__cvta_generic_to_shared((void*)p);
    asm volatile("ldmatrix.sync.aligned.m8n8.x4.shared.b16 {%0,%1,%2,%3}, [%4];\n"
        : "=r"(f[0]), "=r"(f[1]), "=r"(f[2]), "=r"(f[3]) : "r"(s));
}

__device__ __forceinline__ void cp_async16(uint32_t saddr, const void* gptr) {
    asm volatile("cp.async.cg.shared.global [%0], [%1], 16;\n" :: "r"(saddr), "l"(gptr));
}
__device__ __forceinline__ void cp_commit() {
    asm volatile("cp.async.commit_group;\n");
}
template<int N>
__device__ __forceinline__ void cp_wait() {
    asm volatile("cp.async.wait_group %0;\n" :: "n"(N));
}

// ---------------------------------------------------------------------------
// TF32 tensor-core GEMM: C[M,N] = epi( A[M,K] @ W[N,K]^T + bias[N] [+res] )
// CTA tile 128x64, BK=16, 4-stage cp.async pipeline, 256 thr = 8 warps
// (4x2 grid, warp tile 32x32). 2 CTAs/SM co-resident -> independent barrier
// domains hide sync/pipeline bubbles (round-7: 1 CTA/SM left issue at 28%).
// Smem rows padded to 20 floats (80B: 16B-aligned cp.async dst, conflict-free
// ldmatrix phases). Dynamic smem = 4 * 15360 B = 61440 B.
// Requires M%128==0, N%64==0, K%16==0.
// ---------------------------------------------------------------------------
#define SM_STRIDE 20
#define STAGE_FLOATS ((128 + 64) * SM_STRIDE)  // A(2560) + B(1280) = 3840
#define STAGE_BYTES  (STAGE_FLOATS * 4)        // 15360
#define GEMM_STAGES  4
#define GEMM_SMEM    (GEMM_STAGES * STAGE_BYTES)  // 61440

template<int ACT, bool RES>
__global__ __launch_bounds__(256, 2)
void tgemm_kernel(const float* __restrict__ A,
                  const float* __restrict__ W,
                  const float* __restrict__ bias,
                  const float* __restrict__ res,
                  float* __restrict__ C,
                  int M, int N, int K)
{
    extern __shared__ float smem[];

    const int bm   = blockIdx.y * 128;
    const int bn   = blockIdx.x * 64;
    const int tid  = threadIdx.x;
    const int warp = tid >> 5;
    const int lane = tid & 31;
    const int wm   = (warp >> 1) * 32;   // 4 warp rows
    const int wn   = (warp & 1) * 32;    // 2 warp cols

    // ---- gmem -> smem: A rows r0,r0+64 (2 cp), B row r0 (1 cp) ----
    const int r0 = tid >> 2;             // row 0..63
    const int kq = (tid & 3) * 4;        // float offset within 16-float k-slab
    const float* Ag = A + (size_t)(bm + r0) * K + kq;   // + 64*K for second row
    const float* Wg = W + (size_t)(bn + r0) * K + kq;
    const size_t a64 = (size_t)64 * K;

    const uint32_t sbase = (uint32_t)__cvta_generic_to_shared((void*)smem);
    const uint32_t aoff0 = (uint32_t)(r0 * SM_STRIDE + kq) * 4;           // bytes
    const uint32_t aoff1 = aoff0 + (uint32_t)(64 * SM_STRIDE) * 4;
    const uint32_t boff  = (uint32_t)(128 * SM_STRIDE * 4) + aoff0;

    // ---- ldmatrix per-lane source offsets (verified mapping, unchanged) ----
    const int lg   = lane >> 3;
    const int lr   = lane & 7;
    const int lrow = (lg & 1) * 8 + lr;
    const int lcol = (lg >> 1) * 4;

    float acc[2][4][4];
    #pragma unroll
    for (int mt = 0; mt < 2; mt++)
        #pragma unroll
        for (int nt = 0; nt < 4; nt++)
            #pragma unroll
            for (int i = 0; i < 4; i++) acc[mt][nt][i] = 0.0f;

    const int nk = K >> 4;

    // ---- prologue: stages 0..2 in flight ----
    #pragma unroll
    for (int s = 0; s < GEMM_STAGES - 1; s++) {
        const float* a = Ag + (size_t)s * 16;
        const float* w = Wg + (size_t)s * 16;
        const uint32_t base = sbase + s * STAGE_BYTES;
        cp_async16(base + aoff0, a);
        cp_async16(base + aoff1, a + a64);
        cp_async16(base + boff,  w);
        cp_commit();
    }

    int s_cur = 0, s_nxt = GEMM_STAGES - 1;
    for (int kt = 0; kt < nk; kt++) {
        cp_wait<GEMM_STAGES - 2>();
        __syncthreads();

        if (kt + GEMM_STAGES - 1 < nk) {
            const float* a = Ag + (size_t)(kt + GEMM_STAGES - 1) * 16;
            const float* w = Wg + (size_t)(kt + GEMM_STAGES - 1) * 16;
            const uint32_t base = sbase + s_nxt * STAGE_BYTES;
            cp_async16(base + aoff0, a);
            cp_async16(base + aoff1, a + a64);
            cp_async16(base + boff,  w);
        }
        cp_commit();   // empty groups at the tail keep wait_group counts valid

        const float* Ac = smem + s_cur * STAGE_FLOATS;
        const float* Bc = Ac + 128 * SM_STRIDE;

        #pragma unroll
        for (int ks = 0; ks < 2; ks++) {
            uint32_t afr[2][4];
            uint32_t bfr[4][2];
            #pragma unroll
            for (int mt = 0; mt < 2; mt++)
                ldm_x4(afr[mt], &Ac[(wm + mt * 16 + lrow) * SM_STRIDE + ks * 8 + lcol]);
            #pragma unroll
            for (int j = 0; j < 2; j++) {
                uint32_t t[4];
                ldm_x4(t, &Bc[(wn + j * 16 + lrow) * SM_STRIDE + ks * 8 + lcol]);
                bfr[2 * j][0]     = t[0];
                bfr[2 * j + 1][0] = t[1];
                bfr[2 * j][1]     = t[2];
                bfr[2 * j + 1][1] = t[3];
            }
            #pragma unroll
            for (int mt = 0; mt < 2; mt++)
                #pragma unroll
                for (int nt = 0; nt < 4; nt++)
                    mma_tf32(acc[mt][nt], afr[mt], bfr[nt]);
        }

        s_cur = (s_cur + 1 == GEMM_STAGES) ? 0 : s_cur + 1;
        s_nxt = (s_nxt + 1 == GEMM_STAGES) ? 0 : s_nxt + 1;
    }

    // ---- epilogue: bias (+gelu) (+res), float2 stores ----
    const int g  = lane >> 2;
    const int cc = (lane & 3) * 2;
    #pragma unroll
    for (int mt = 0; mt < 2; mt++) {
        const int row = bm + wm + mt * 16 + g;   // and row+8
        #pragma unroll
        for (int nt = 0; nt < 4; nt++) {
            const int col = bn + wn + nt * 8 + cc;
            const float2 bv = *(const float2*)&bias[col];
            float v0 = acc[mt][nt][0] + bv.x;
            float v1 = acc[mt][nt][1] + bv.y;
            float v2 = acc[mt][nt][2] + bv.x;
            float v3 = acc[mt][nt][3] + bv.y;
            if (ACT == 1) {
                v0 = gelu_exact(v0); v1 = gelu_exact(v1);
                v2 = gelu_exact(v2); v3 = gelu_exact(v3);
            }
            if (RES) {
                const float2 ra = *(const float2*)&res[(size_t)row * N + col];
                const float2 rb = *(const float2*)&res[(size_t)(row + 8) * N + col];
                v0 += ra.x; v1 += ra.y; v2 += rb.x; v3 += rb.y;
            }
            float2 o0 = {v0, v1};
            float2 o1 = {v2, v3};
            *(float2*)&C[(size_t)row * N + col]       = o0;
            *(float2*)&C[(size_t)(row + 8) * N + col] = o1;
        }
    }
}

// ---------------------------------------------------------------------------
// LayerNorm over last dim (E=512). One block (128 threads, float4) per row.
// ---------------------------------------------------------------------------
__global__ void ln_kernel(const float* __restrict__ x,
                          const float* __restrict__ g,
                          const float* __restrict__ b,
                          float* __restrict__ y)
{
    const int row = blockIdx.x;
    const int t   = threadIdx.x;  // 0..127
    const float4 v = ((const float4*)(x + (size_t)row * EMB))[t];

    float s  = v.x + v.y + v.z + v.w;
    float ss = v.x * v.x + v.y * v.y + v.z * v.z + v.w * v.w;
    #pragma unroll
    for (int o = 16; o; o >>= 1) {
        s  += __shfl_xor_sync(0xffffffffu, s,  o);
        ss += __shfl_xor_sync(0xffffffffu, ss, o);
    }
    __shared__ float sm[4], sm2[4];
    if ((t & 31) == 0) { sm[t >> 5] = s; sm2[t >> 5] = ss; }
    __syncthreads();
    s  = sm[0]  + sm[1]  + sm[2]  + sm[3];
    ss = sm2[0] + sm2[1] + sm2[2] + sm2[3];

    const float mean = s * (1.0f / EMB);
    const float var  = ss * (1.0f / EMB) - mean * mean;
    const float inv  = rsqrtf(var + 1e-5f);

    const float4 gg = ((const float4*)g)[t];
    const float4 bb = ((const float4*)b)[t];
    float4 o;
    o.x = (v.x - mean) * inv * gg.x + bb.x;
    o.y = (v.y - mean) * inv * gg.y + bb.y;
    o.z = (v.z - mean) * inv * gg.z + bb.z;
    o.w = (v.w - mean) * inv * gg.w + bb.w;
    ((float4*)(y + (size_t)row * EMB))[t] = o;
}

// ---------------------------------------------------------------------------
// Windowed attention. One warp per (batch, head, query); <=9 unmasked keys.
// qkv layout: [MROWS, 3*EMB] = [q | k | v], head h at column h*64.
// ---------------------------------------------------------------------------
__global__ void attn_kernel(const float* __restrict__ qkv,
                            float* __restrict__ out)
{
    const int gw   = blockIdx.x * 8 + (threadIdx.x >> 5);
    const int lane = threadIdx.x & 31;

    const int qpos = gw & (SEQ - 1);
    const int h    = (gw >> 10) & (HEADS - 1);
    const int b    = gw >> 13;

    const int row = b * SEQ + qpos;
    const float* qp = qkv + (size_t)row * (3 * EMB) + h * HDIM;
    const float q0 = qp[lane]      * 0.125f;   // 1/sqrt(64)
    const float q1 = qp[lane + 32] * 0.125f;

    const int y = qpos >> 5;
    const int x = qpos & 31;

    float s[9];
    int   krow[9];
    int   n = 0;
    #pragma unroll
    for (int dy = -1; dy <= 1; dy++) {
        #pragma unroll
        for (int dx = -1; dx <= 1; dx++) {
            const int ny = y + dy, nx = x + dx;
            if (ny < 0 || ny >= GRID_W || nx < 0 || nx >= GRID_W) continue;
            const int kr = b * SEQ + (ny << 5) + nx;
            const float* kp = qkv + (size_t)kr * (3 * EMB) + EMB + h * HDIM;
            float p = q0 * kp[lane] + q1 * kp[lane + 32];
            #pragma unroll
            for (int o = 16; o; o >>= 1) p += __shfl_xor_sync(0xffffffffu, p, o);
            s[n] = p; krow[n] = kr; n++;
        }
    }

    float mx = s[0];
    for (int j = 1; j < n; j++) mx = fmaxf(mx, s[j]);
    float sum = 0.0f;
    for (int j = 0; j < n; j++) { s[j] = expf(s[j] - mx); sum += s[j]; }
    const float inv = 1.0f / sum;

    float o0 = 0.0f, o1 = 0.0f;
    for (int j = 0; j < n; j++) {
        const float* vp = qkv + (size_t)krow[j] * (3 * EMB) + 2 * EMB + h * HDIM;
        const float a = s[j] * inv;
        o0 = fmaf(a, vp[lane],      o0);
        o1 = fmaf(a, vp[lane + 32], o1);
    }
    out[(size_t)row * EMB + h * HDIM + lane]      = o0;
    out[(size_t)row * EMB + h * HDIM + lane + 32] = o1;
}

// ---------------------------------------------------------------------------
// Elementwise helper
// ---------------------------------------------------------------------------
__global__ void add_kernel(const float* __restrict__ a, const float* __restrict__ b,
                           float* __restrict__ dst, int n4) {
    int i = blockIdx.x * blockDim.x + threadIdx.x;
    if (i < n4) {
        float4 va = ((const float4*)a)[i];
        float4 vb = ((const float4*)b)[i];
        float4 o = {va.x + vb.x, va.y + vb.y, va.z + vb.z, va.w + vb.w};
        ((float4*)dst)[i] = o;
    }
}

// ---------------------------------------------------------------------------
// Host orchestration
// ---------------------------------------------------------------------------
static inline void run_gemm(int act, bool res_flag,
                            const float* A, const float* W, const float* bias,
                            const float* res, float* C, int M, int N, int K,
                            cudaStream_t s)
{
    dim3 grid(N / 64, M / 128);
    if (act == 0 && !res_flag)      tgemm_kernel<0, false><<<grid, 256, GEMM_SMEM, s>>>(A, W, bias, res, C, M, N, K);
    else if (act == 0 && res_flag)  tgemm_kernel<0, true ><<<grid, 256, GEMM_SMEM, s>>>(A, W, bias, res, C, M, N, K);
    else if (act == 1 && !res_flag) tgemm_kernel<1, false><<<grid, 256, GEMM_SMEM, s>>>(A, W, bias, res, C, M, N, K);
    else                            tgemm_kernel<1, true ><<<grid, 256, GEMM_SMEM, s>>>(A, W, bias, res, C, M, N, K);
}

extern "C" void kernel_launch(void* const* d_in, const int* in_sizes, int n_in,
                              void* d_out, int out_size)
{
    (void)in_sizes; (void)n_in; (void)out_size;
    const float* x      = (const float*)d_in[0];
    // d_in[1] = mask : structure exploited analytically (3x3 window, 32x32 grid)
    const float* in_w   = (const float*)d_in[2];
    const float* in_b   = (const float*)d_in[3];
    const float* out_w  = (const float*)d_in[4];
    const float* out_b  = (const float*)d_in[5];
    const float* ln1_g  = (const float*)d_in[6];
    const float* ln1_b  = (const float*)d_in[7];
    const float* ln2_g  = (const float*)d_in[8];
    const float* ln2_b  = (const float*)d_in[9];
    const float* ff1_w  = (const float*)d_in[10];
    const float* ff1_b  = (const float*)d_in[11];
    const float* ff2_w  = (const float*)d_in[12];
    const float* ff2_b  = (const float*)d_in[13];
    const float* mlp_ln_g = (const float*)d_in[14];
    const float* mlp_ln_b = (const float*)d_in[15];
    const float* mlp_w1 = (const float*)d_in[16];
    const float* mlp_b1 = (const float*)d_in[17];
    const float* mlp_w2 = (const float*)d_in[18];
    const float* mlp_b2 = (const float*)d_in[19];
    float* out = (float*)d_out;

    // opt-in to >48KB dynamic smem (host-side, idempotent, not captured)
    cudaFuncSetAttribute(tgemm_kernel<0, false>, cudaFuncAttributeMaxDynamicSharedMemorySize, GEMM_SMEM);
    cudaFuncSetAttribute(tgemm_kernel<0, true >, cudaFuncAttributeMaxDynamicSharedMemorySize, GEMM_SMEM);
    cudaFuncSetAttribute(tgemm_kernel<1, false>, cudaFuncAttributeMaxDynamicSharedMemorySize, GEMM_SMEM);
    cudaFuncSetAttribute(tgemm_kernel<1, true >, cudaFuncAttributeMaxDynamicSharedMemorySize, GEMM_SMEM);

    float *h, *ln, *qkv, *att, *ff, *mid;
    cudaGetSymbolAddress((void**)&h,   g_h);
    cudaGetSymbolAddress((void**)&ln,  g_ln);
    cudaGetSymbolAddress((void**)&qkv, g_qkv);
    cudaGetSymbolAddress((void**)&att, g_att);
    cudaGetSymbolAddress((void**)&ff,  g_ff);
    cudaGetSymbolAddress((void**)&mid, g_mid);

    cudaStream_t s = 0;
    const int M = MROWS, E = EMB;
    const int n4  = M * E / 4;
    const int eb  = 256;
    const int eg  = (n4 + eb - 1) / eb;

    const float* cur = x;   // residual stream; layer 0 reads the input directly

    for (int l = 0; l < LAYERS; l++) {
        const float* iw  = in_w  + (size_t)l * 3 * E * E;
        const float* ib  = in_b  + (size_t)l * 3 * E;
        const float* ow  = out_w + (size_t)l * E * E;
        const float* ob  = out_b + (size_t)l * E;
        const float* l1g = ln1_g + (size_t)l * E;
        const float* l1b = ln1_b + (size_t)l * E;
        const float* l2g = ln2_g + (size_t)l * E;
        const float* l2b = ln2_b + (size_t)l * E;
        const float* f1w = ff1_w + (size_t)l * E * E;
        const float* f1b = ff1_b + (size_t)l * E;
        const float* f2w = ff2_w + (size_t)l * E * E;
        const float* f2b = ff2_b + (size_t)l * E;

        // h_ln = LN1(cur)
        ln_kernel<<<M, 128, 0, s>>>(cur, l1g, l1b, ln);
        // qkv = h_ln @ in_w^T + in_b
        run_gemm(0, false, ln, iw, ib, nullptr, qkv, M, 3 * E, E, s);
        // att = windowed_softmax_attention(qkv)
        attn_kernel<<<(BATCH * HEADS * SEQ) / 8, 256, 0, s>>>(qkv, att);
        // h = cur + att @ out_w^T + out_b
        run_gemm(0, true, att, ow, ob, cur, h, M, E, E, s);
        cur = h;
        // h_ln = LN2(h)
        ln_kernel<<<M, 128, 0, s>>>(h, l2g, l2b, ln);
        // ff = gelu(h_ln @ ff1_w^T + ff1_b)
        run_gemm(1, false, ln, f1w, f1b, nullptr, ff, M, E, E, s);
        // h = h + ff @ ff2_w^T + ff2_b
        run_gemm(0, true, ff, f2w, f2b, h, h, M, E, E, s);
    }

    // out = x + h
    add_kernel<<<eg, eb, 0, s>>>(x, h, out, n4);
    // ln = LN(out)
    ln_kernel<<<M, 128, 0, s>>>(out, mlp_ln_g, mlp_ln_b, ln);
    // mid = gelu(ln @ mlp_w1^T + mlp_b1)   [M, 2048]
    run_gemm(1, false, ln, mlp_w1, mlp_b1, nullptr, mid, M, 4 * E, E, s);
    // out = out + mid @ mlp_w2^T + mlp_b2
    run_gemm(0, true, mid, mlp_w2, mlp_b2, out, out, M, E, 4 * E, s);
}

// round 10
// speedup vs baseline: 1.1547x; 1.0466x over previous
#include <cuda_runtime.h>
#include <cuda_bf16.h>
#include <math.h>
#include <stdint.h>

// ---------------------------------------------------------------------------
// Problem constants (fixed by setup_inputs)
// ---------------------------------------------------------------------------
#define BATCH   4
#define SEQ     1024          // 32*32 grid
#define EMB     512
#define HEADS   8
#define HDIM    64            // EMB / HEADS
#define LAYERS  4
#define MROWS   (BATCH * SEQ) // 4096
#define GRID_W  32            // sqrt(SEQ)

// ---------------------------------------------------------------------------
// Scratch (device globals; no allocation allowed)
// ---------------------------------------------------------------------------
__device__ float g_h   [MROWS * EMB];
__device__ float g_ln  [MROWS * EMB];
__device__ float g_qkv [MROWS * 3 * EMB];
__device__ float g_att [MROWS * EMB];
__device__ float g_ff  [MROWS * EMB];
__device__ float g_mid [MROWS * 4 * EMB];

// ---------------------------------------------------------------------------
// GELU (exact, erf-based — matches jax.nn.gelu(approximate=False))
// ---------------------------------------------------------------------------
__device__ __forceinline__ float gelu_exact(float x) {
    return 0.5f * x * (1.0f + erff(x * 0.70710678118654752440f));
}

// ---------------------------------------------------------------------------
// Tensor-core primitives (TF32 m16n8k8) — legacy mma.sync path (sm_100 target
// has no tcgen05; confirmed by round-9 ptxas failure).
// mma asm intentionally NON-volatile: pure register op, data deps enforce
// correctness, lets ptxas interleave with ldmatrix for latency hiding.
// ---------------------------------------------------------------------------
__device__ __forceinline__ void mma_tf32(float* d, const uint32_t* a, const uint32_t* b) {
    asm("mma.sync.aligned.m16n8k8.row.col.f32.tf32.tf32.f32 "
        "{%0,%1,%2,%3}, {%4,%5,%6,%7}, {%8,%9}, {%0,%1,%2,%3};\n"
        : "+f"(d[0]), "+f"(d[1]), "+f"(d[2]), "+f"(d[3])
        : "r"(a[0]), "r"(a[1]), "r"(a[2]), "r"(a[3]), "r"(b[0]), "r"(b[1]));
}

__device__ __forceinline__ void ldm_x4(uint32_t* f, const float* p) {
    uint32_t s = (uint32_t)__cvta_generic_to_shared((void*)p);
    asm volatile("ldmatrix.sync.aligned.m8n8.x4.shared.b16 {%0,%1,%2,%3}, [%4];\n"
        : "=r"(f[0]), "=r"(f[1]), "=r"(f[2]), "=r"(f[3]) : "r"(s));
}

__device__ __forceinline__ void cp_async16(uint32_t saddr, const void* gptr) {
    asm volatile("cp.async.cg.shared.global [%0], [%1], 16;\n" :: "r"(saddr), "l"(gptr));
}
__device__ __forceinline__ void cp_commit() {
    asm volatile("cp.async.commit_group;\n");
}
template<int N>
__device__ __forceinline__ void cp_wait() {
    asm volatile("cp.async.wait_group %0;\n" :: "n"(N));
}

// ---------------------------------------------------------------------------
// TF32 tensor-core GEMM: C[M,N] = epi( A[M,K] @ W[N,K]^T + bias[N] [+res] )
// CTA tile 128x128, BK=32 (half the barriers of BK=16), 4-stage cp.async
// ring, 512 thr = 16 warps (4x4 grid, warp tile 32x32, 4 warps/SMSP).
// Fragment double-buffering: ldmatrix for ks+1 issued before the MMAs of ks.
// Smem rows padded to 36 floats (144B): 16B-aligned cp.async dst; ldmatrix
// 8-row phase hits banks {4r..4r+3 mod 32} -> conflict-free.
// Requires M%128==0, N%128==0, K%32==0.
// ---------------------------------------------------------------------------
#define SMS          36                       // floats per padded row
#define A_TILE_FL    (128 * SMS)              // 4608 floats
#define STAGE_FLOATS (2 * A_TILE_FL)          // A + B = 9216 floats
#define STAGE_BYTES  (STAGE_FLOATS * 4)       // 36864
#define GEMM_STAGES  4
#define GEMM_SMEM    (GEMM_STAGES * STAGE_BYTES)   // 147456 (144 KB)

template<int ACT, bool RES>
__global__ __launch_bounds__(512, 1)
void tgemm_kernel(const float* __restrict__ A,
                  const float* __restrict__ W,
                  const float* __restrict__ bias,
                  const float* __restrict__ res,
                  float* __restrict__ C,
                  int M, int N, int K)
{
    extern __shared__ float smem[];

    const int bm   = blockIdx.y * 128;
    const int bn   = blockIdx.x * 128;
    const int tid  = threadIdx.x;
    const int warp = tid >> 5;
    const int lane = tid & 31;
    const int wm   = (warp >> 2) * 32;   // 4 warp rows
    const int wn   = (warp & 3) * 32;    // 4 warp cols

    // ---- gmem -> smem: rows r0, r0+64 for A and B; one float4 unit each ----
    const int r0 = tid >> 3;             // 0..63
    const int u4 = (tid & 7) * 4;        // float offset within 32-float row
    const float* Ag = A + (size_t)(bm + r0) * K + u4;
    const float* Wg = W + (size_t)(bn + r0) * K + u4;
    const size_t g64 = (size_t)64 * K;

    const uint32_t sbase = (uint32_t)__cvta_generic_to_shared((void*)smem);
    const uint32_t aoff0 = (uint32_t)(r0 * SMS + u4) * 4;            // bytes
    const uint32_t aoff1 = aoff0 + (uint32_t)(64 * SMS) * 4;
    const uint32_t boff0 = (uint32_t)(A_TILE_FL * 4) + aoff0;
    const uint32_t boff1 = (uint32_t)(A_TILE_FL * 4) + aoff1;

    // ---- ldmatrix per-lane source offsets (verified mapping) ----
    const int lg   = lane >> 3;
    const int lr   = lane & 7;
    const int lrow = (lg & 1) * 8 + lr;
    const int lcol = (lg >> 1) * 4;

    float acc[2][4][4];
    #pragma unroll
    for (int mt = 0; mt < 2; mt++)
        #pragma unroll
        for (int nt = 0; nt < 4; nt++)
            #pragma unroll
            for (int i = 0; i < 4; i++) acc[mt][nt][i] = 0.0f;

    const int nk = K >> 5;   // BK=32

    // ---- prologue: stages 0..2 in flight ----
    #pragma unroll
    for (int s = 0; s < GEMM_STAGES - 1; s++) {
        const float* a = Ag + (size_t)s * 32;
        const float* w = Wg + (size_t)s * 32;
        const uint32_t base = sbase + s * STAGE_BYTES;
        cp_async16(base + aoff0, a);
        cp_async16(base + aoff1, a + g64);
        cp_async16(base + boff0, w);
        cp_async16(base + boff1, w + g64);
        cp_commit();
    }

    int s_cur = 0, s_nxt = GEMM_STAGES - 1;
    for (int kt = 0; kt < nk; kt++) {
        cp_wait<GEMM_STAGES - 2>();
        __syncthreads();

        if (kt + GEMM_STAGES - 1 < nk) {
            const float* a = Ag + (size_t)(kt + GEMM_STAGES - 1) * 32;
            const float* w = Wg + (size_t)(kt + GEMM_STAGES - 1) * 32;
            const uint32_t base = sbase + s_nxt * STAGE_BYTES;
            cp_async16(base + aoff0, a);
            cp_async16(base + aoff1, a + g64);
            cp_async16(base + boff0, w);
            cp_async16(base + boff1, w + g64);
        }
        cp_commit();   // empty groups at the tail keep wait counts valid

        const float* Ac = smem + s_cur * STAGE_FLOATS;
        const float* Bc = Ac + A_TILE_FL;

        // ---- 4 k-steps of 8 floats, fragment double-buffered ----
        uint32_t afr[2][2][4];
        uint32_t bfr[2][4][2];

        // load ks=0 into buffer 0
        #pragma unroll
        for (int mt = 0; mt < 2; mt++)
            ldm_x4(afr[0][mt], &Ac[(wm + mt * 16 + lrow) * SMS + lcol]);
        #pragma unroll
        for (int j = 0; j < 2; j++) {
            uint32_t t[4];
            ldm_x4(t, &Bc[(wn + j * 16 + lrow) * SMS + lcol]);
            bfr[0][2 * j][0]     = t[0];
            bfr[0][2 * j + 1][0] = t[1];
            bfr[0][2 * j][1]     = t[2];
            bfr[0][2 * j + 1][1] = t[3];
        }

        #pragma unroll
        for (int ks = 0; ks < 4; ks++) {
            const int cb = ks & 1;
            if (ks < 3) {
                const int nb = cb ^ 1;
                const int kc = (ks + 1) * 8;
                #pragma unroll
                for (int mt = 0; mt < 2; mt++)
                    ldm_x4(afr[nb][mt], &Ac[(wm + mt * 16 + lrow) * SMS + kc + lcol]);
                #pragma unroll
                for (int j = 0; j < 2; j++) {
                    uint32_t t[4];
                    ldm_x4(t, &Bc[(wn + j * 16 + lrow) * SMS + kc + lcol]);
                    bfr[nb][2 * j][0]     = t[0];
                    bfr[nb][2 * j + 1][0] = t[1];
                    bfr[nb][2 * j][1]     = t[2];
                    bfr[nb][2 * j + 1][1] = t[3];
                }
            }
            #pragma unroll
            for (int mt = 0; mt < 2; mt++)
                #pragma unroll
                for (int nt = 0; nt < 4; nt++)
                    mma_tf32(acc[mt][nt], afr[cb][mt], bfr[cb][nt]);
        }

        s_cur = (s_cur + 1 == GEMM_STAGES) ? 0 : s_cur + 1;
        s_nxt = (s_nxt + 1 == GEMM_STAGES) ? 0 : s_nxt + 1;
    }

    // ---- epilogue: bias (+gelu) (+res), float2 stores ----
    const int g  = lane >> 2;
    const int cc = (lane & 3) * 2;
    #pragma unroll
    for (int mt = 0; mt < 2; mt++) {
        const int row = bm + wm + mt * 16 + g;   // and row+8
        #pragma unroll
        for (int nt = 0; nt < 4; nt++) {
            const int col = bn + wn + nt * 8 + cc;
            const float2 bv = *(const float2*)&bias[col];
            float v0 = acc[mt][nt][0] + bv.x;
            float v1 = acc[mt][nt][1] + bv.y;
            float v2 = acc[mt][nt][2] + bv.x;
            float v3 = acc[mt][nt][3] + bv.y;
            if (ACT == 1) {
                v0 = gelu_exact(v0); v1 = gelu_exact(v1);
                v2 = gelu_exact(v2); v3 = gelu_exact(v3);
            }
            if (RES) {
                const float2 ra = *(const float2*)&res[(size_t)row * N + col];
                const float2 rb = *(const float2*)&res[(size_t)(row + 8) * N + col];
                v0 += ra.x; v1 += ra.y; v2 += rb.x; v3 += rb.y;
            }
            float2 o0 = {v0, v1};
            float2 o1 = {v2, v3};
            *(float2*)&C[(size_t)row * N + col]       = o0;
            *(float2*)&C[(size_t)(row + 8) * N + col] = o1;
        }
    }
}

// ---------------------------------------------------------------------------
// LayerNorm over last dim (E=512). One block (128 threads, float4) per row.
// ---------------------------------------------------------------------------
__global__ void ln_kernel(const float* __restrict__ x,
                          const float* __restrict__ g,
                          const float* __restrict__ b,
                          float* __restrict__ y)
{
    const int row = blockIdx.x;
    const int t   = threadIdx.x;  // 0..127
    const float4 v = ((const float4*)(x + (size_t)row * EMB))[t];

    float s  = v.x + v.y + v.z + v.w;
    float ss = v.x * v.x + v.y * v.y + v.z * v.z + v.w * v.w;
    #pragma unroll
    for (int o = 16; o; o >>= 1) {
        s  += __shfl_xor_sync(0xffffffffu, s,  o);
        ss += __shfl_xor_sync(0xffffffffu, ss, o);
    }
    __shared__ float sm[4], sm2[4];
    if ((t & 31) == 0) { sm[t >> 5] = s; sm2[t >> 5] = ss; }
    __syncthreads();
    s  = sm[0]  + sm[1]  + sm[2]  + sm[3];
    ss = sm2[0] + sm2[1] + sm2[2] + sm2[3];

    const float mean = s * (1.0f / EMB);
    const float var  = ss * (1.0f / EMB) - mean * mean;
    const float inv  = rsqrtf(var + 1e-5f);

    const float4 gg = ((const float4*)g)[t];
    const float4 bb = ((const float4*)b)[t];
    float4 o;
    o.x = (v.x - mean) * inv * gg.x + bb.x;
    o.y = (v.y - mean) * inv * gg.y + bb.y;
    o.z = (v.z - mean) * inv * gg.z + bb.z;
    o.w = (v.w - mean) * inv * gg.w + bb.w;
    ((float4*)(y + (size_t)row * EMB))[t] = o;
}

// ---------------------------------------------------------------------------
// Windowed attention. One warp per (batch, head, query); <=9 unmasked keys.
// qkv layout: [MROWS, 3*EMB] = [q | k | v], head h at column h*64.
// ---------------------------------------------------------------------------
__global__ void attn_kernel(const float* __restrict__ qkv,
                            float* __restrict__ out)
{
    const int gw   = blockIdx.x * 8 + (threadIdx.x >> 5);
    const int lane = threadIdx.x & 31;

    const int qpos = gw & (SEQ - 1);
    const int h    = (gw >> 10) & (HEADS - 1);
    const int b    = gw >> 13;

    const int row = b * SEQ + qpos;
    const float* qp = qkv + (size_t)row * (3 * EMB) + h * HDIM;
    const float q0 = qp[lane]      * 0.125f;   // 1/sqrt(64)
    const float q1 = qp[lane + 32] * 0.125f;

    const int y = qpos >> 5;
    const int x = qpos & 31;

    float s[9];
    int   krow[9];
    int   n = 0;
    #pragma unroll
    for (int dy = -1; dy <= 1; dy++) {
        #pragma unroll
        for (int dx = -1; dx <= 1; dx++) {
            const int ny = y + dy, nx = x + dx;
            if (ny < 0 || ny >= GRID_W || nx < 0 || nx >= GRID_W) continue;
            const int kr = b * SEQ + (ny << 5) + nx;
            const float* kp = qkv + (size_t)kr * (3 * EMB) + EMB + h * HDIM;
            float p = q0 * kp[lane] + q1 * kp[lane + 32];
            #pragma unroll
            for (int o = 16; o; o >>= 1) p += __shfl_xor_sync(0xffffffffu, p, o);
            s[n] = p; krow[n] = kr; n++;
        }
    }

    float mx = s[0];
    for (int j = 1; j < n; j++) mx = fmaxf(mx, s[j]);
    float sum = 0.0f;
    for (int j = 0; j < n; j++) { s[j] = expf(s[j] - mx); sum += s[j]; }
    const float inv = 1.0f / sum;

    float o0 = 0.0f, o1 = 0.0f;
    for (int j = 0; j < n; j++) {
        const float* vp = qkv + (size_t)krow[j] * (3 * EMB) + 2 * EMB + h * HDIM;
        const float a = s[j] * inv;
        o0 = fmaf(a, vp[lane],      o0);
        o1 = fmaf(a, vp[lane + 32], o1);
    }
    out[(size_t)row * EMB + h * HDIM + lane]      = o0;
    out[(size_t)row * EMB + h * HDIM + lane + 32] = o1;
}

// ---------------------------------------------------------------------------
// Elementwise helper
// ---------------------------------------------------------------------------
__global__ void add_kernel(const float* __restrict__ a, const float* __restrict__ b,
                           float* __restrict__ dst, int n4) {
    int i = blockIdx.x * blockDim.x + threadIdx.x;
    if (i < n4) {
        float4 va = ((const float4*)a)[i];
        float4 vb = ((const float4*)b)[i];
        float4 o = {va.x + vb.x, va.y + vb.y, va.z + vb.z, va.w + vb.w};
        ((float4*)dst)[i] = o;
    }
}

// ---------------------------------------------------------------------------
// Host orchestration
// ---------------------------------------------------------------------------
static inline void run_gemm(int act, bool res_flag,
                            const float* A, const float* W, const float* bias,
                            const float* res, float* C, int M, int N, int K,
                            cudaStream_t s)
{
    dim3 grid(N / 128, M / 128);
    if (act == 0 && !res_flag)      tgemm_kernel<0, false><<<grid, 512, GEMM_SMEM, s>>>(A, W, bias, res, C, M, N, K);
    else if (act == 0 && res_flag)  tgemm_kernel<0, true ><<<grid, 512, GEMM_SMEM, s>>>(A, W, bias, res, C, M, N, K);
    else if (act == 1 && !res_flag) tgemm_kernel<1, false><<<grid, 512, GEMM_SMEM, s>>>(A, W, bias, res, C, M, N, K);
    else                            tgemm_kernel<1, true ><<<grid, 512, GEMM_SMEM, s>>>(A, W, bias, res, C, M, N, K);
}

extern "C" void kernel_launch(void* const* d_in, const int* in_sizes, int n_in,
                              void* d_out, int out_size)
{
    (void)in_sizes; (void)n_in; (void)out_size;
    const float* x      = (const float*)d_in[0];
    // d_in[1] = mask : structure exploited analytically (3x3 window, 32x32 grid)
    const float* in_w   = (const float*)d_in[2];
    const float* in_b   = (const float*)d_in[3];
    const float* out_w  = (const float*)d_in[4];
    const float* out_b  = (const float*)d_in[5];
    const float* ln1_g  = (const float*)d_in[6];
    const float* ln1_b  = (const float*)d_in[7];
    const float* ln2_g  = (const float*)d_in[8];
    const float* ln2_b  = (const float*)d_in[9];
    const float* ff1_w  = (const float*)d_in[10];
    const float* ff1_b  = (const float*)d_in[11];
    const float* ff2_w  = (const float*)d_in[12];
    const float* ff2_b  = (const float*)d_in[13];
    const float* mlp_ln_g = (const float*)d_in[14];
    const float* mlp_ln_b = (const float*)d_in[15];
    const float* mlp_w1 = (const float*)d_in[16];
    const float* mlp_b1 = (const float*)d_in[17];
    const float* mlp_w2 = (const float*)d_in[18];
    const float* mlp_b2 = (const float*)d_in[19];
    float* out = (float*)d_out;

    // opt-in to >48KB dynamic smem (host-side, idempotent, not captured)
    cudaFuncSetAttribute(tgemm_kernel<0, false>, cudaFuncAttributeMaxDynamicSharedMemorySize, GEMM_SMEM);
    cudaFuncSetAttribute(tgemm_kernel<0, true >, cudaFuncAttributeMaxDynamicSharedMemorySize, GEMM_SMEM);
    cudaFuncSetAttribute(tgemm_kernel<1, false>, cudaFuncAttributeMaxDynamicSharedMemorySize, GEMM_SMEM);
    cudaFuncSetAttribute(tgemm_kernel<1, true >, cudaFuncAttributeMaxDynamicSharedMemorySize, GEMM_SMEM);

    float *h, *ln, *qkv, *att, *ff, *mid;
    cudaGetSymbolAddress((void**)&h,   g_h);
    cudaGetSymbolAddress((void**)&ln,  g_ln);
    cudaGetSymbolAddress((void**)&qkv, g_qkv);
    cudaGetSymbolAddress((void**)&att, g_att);
    cudaGetSymbolAddress((void**)&ff,  g_ff);
    cudaGetSymbolAddress((void**)&mid, g_mid);

    cudaStream_t s = 0;
    const int M = MROWS, E = EMB;
    const int n4  = M * E / 4;
    const int eb  = 256;
    const int eg  = (n4 + eb - 1) / eb;

    const float* cur = x;   // residual stream; layer 0 reads the input directly

    for (int l = 0; l < LAYERS; l++) {
        const float* iw  = in_w  + (size_t)l * 3 * E * E;
        const float* ib  = in_b  + (size_t)l * 3 * E;
        const float* ow  = out_w + (size_t)l * E * E;
        const float* ob  = out_b + (size_t)l * E;
        const float* l1g = ln1_g + (size_t)l * E;
        const float* l1b = ln1_b + (size_t)l * E;
        const float* l2g = ln2_g + (size_t)l * E;
        const float* l2b = ln2_b + (size_t)l * E;
        const float* f1w = ff1_w + (size_t)l * E * E;
        const float* f1b = ff1_b + (size_t)l * E;
        const float* f2w = ff2_w + (size_t)l * E * E;
        const float* f2b = ff2_b + (size_t)l * E;

        // h_ln = LN1(cur)
        ln_kernel<<<M, 128, 0, s>>>(cur, l1g, l1b, ln);
        // qkv = h_ln @ in_w^T + in_b
        run_gemm(0, false, ln, iw, ib, nullptr, qkv, M, 3 * E, E, s);
        // att = windowed_softmax_attention(qkv)
        attn_kernel<<<(BATCH * HEADS * SEQ) / 8, 256, 0, s>>>(qkv, att);
        // h = cur + att @ out_w^T + out_b
        run_gemm(0, true, att, ow, ob, cur, h, M, E, E, s);
        cur = h;
        // h_ln = LN2(h)
        ln_kernel<<<M, 128, 0, s>>>(h, l2g, l2b, ln);
        // ff = gelu(h_ln @ ff1_w^T + ff1_b)
        run_gemm(1, false, ln, f1w, f1b, nullptr, ff, M, E, E, s);
        // h = h + ff @ ff2_w^T + ff2_b
        run_gemm(0, true, ff, f2w, f2b, h, h, M, E, E, s);
    }

    // out = x + h
    add_kernel<<<eg, eb, 0, s>>>(x, h, out, n4);
    // ln = LN(out)
    ln_kernel<<<M, 128, 0, s>>>(out, mlp_ln_g, mlp_ln_b, ln);
    // mid = gelu(ln @ mlp_w1^T + mlp_b1)   [M, 2048]
    run_gemm(1, false, ln, mlp_w1, mlp_b1, nullptr, mid, M, 4 * E, E, s);
    // out = out + mid @ mlp_w2^T + mlp_b2
    run_gemm(0, true, mid, mlp_w2, mlp_b2, out, out, M, E, 4 * E, s);
}

// round 11
// speedup vs baseline: 1.5431x; 1.3364x over previous
#include <cuda_runtime.h>
#include <cuda_fp16.h>
#include <math.h>
#include <stdint.h>

// ---------------------------------------------------------------------------
// Problem constants (fixed by setup_inputs)
// ---------------------------------------------------------------------------
#define BATCH   4
#define SEQ     1024          // 32*32 grid
#define EMB     512
#define HEADS   8
#define HDIM    64            // EMB / HEADS
#define LAYERS  4
#define MROWS   (BATCH * SEQ) // 4096
#define GRID_W  32            // sqrt(SEQ)

// ---------------------------------------------------------------------------
// Scratch (device globals; no allocation allowed)
// ---------------------------------------------------------------------------
__device__ float  g_h    [MROWS * EMB];          // residual stream (fp32)
__device__ float  g_qkv  [MROWS * 3 * EMB];      // QKV (fp32, read by attention)
__device__ __half g_ln16 [MROWS * EMB];          // LN output (fp16 GEMM A)
__device__ __half g_att16[MROWS * EMB];          // attention output (fp16 GEMM A)
__device__ __half g_ff16 [MROWS * EMB];          // FF1 output (fp16 GEMM A)
__device__ __half g_mid16[MROWS * 4 * EMB];      // final-MLP hidden (fp16 GEMM A)
// fp16 weight mirrors (converted每 launch)
__device__ __half g_inw16 [LAYERS * 3 * EMB * EMB];
__device__ __half g_outw16[LAYERS * EMB * EMB];
__device__ __half g_ff1w16[LAYERS * EMB * EMB];
__device__ __half g_ff2w16[LAYERS * EMB * EMB];
__device__ __half g_mw1_16[4 * EMB * EMB];
__device__ __half g_mw2_16[4 * EMB * EMB];

// ---------------------------------------------------------------------------
// GELU (exact, erf-based — matches jax.nn.gelu(approximate=False))
// ---------------------------------------------------------------------------
__device__ __forceinline__ float gelu_exact(float x) {
    return 0.5f * x * (1.0f + erff(x * 0.70710678118654752440f));
}

// ---------------------------------------------------------------------------
// Tensor-core primitives (FP16 m16n8k16, fp32 accumulate).
// mma asm non-volatile: register-only op, data deps enforce correctness,
// lets ptxas interleave with ldmatrix.
// ---------------------------------------------------------------------------
__device__ __forceinline__ void mma_f16(float* d, const uint32_t* a, const uint32_t* b) {
    asm("mma.sync.aligned.m16n8k16.row.col.f32.f16.f16.f32 "
        "{%0,%1,%2,%3}, {%4,%5,%6,%7}, {%8,%9}, {%0,%1,%2,%3};\n"
        : "+f"(d[0]), "+f"(d[1]), "+f"(d[2]), "+f"(d[3])
        : "r"(a[0]), "r"(a[1]), "r"(a[2]), "r"(a[3]), "r"(b[0]), "r"(b[1]));
}

__device__ __forceinline__ void ldm_x4h(uint32_t* f, const __half* p) {
    uint32_t s = (uint32_t)__cvta_generic_to_shared((void*)p);
    asm volatile("ldmatrix.sync.aligned.m8n8.x4.shared.b16 {%0,%1,%2,%3}, [%4];\n"
        : "=r"(f[0]), "=r"(f[1]), "=r"(f[2]), "=r"(f[3]) : "r"(s));
}

__device__ __forceinline__ void cp_async16(uint32_t saddr, const void* gptr) {
    asm volatile("cp.async.cg.shared.global [%0], [%1], 16;\n" :: "r"(saddr), "l"(gptr));
}
__device__ __forceinline__ void cp_commit() {
    asm volatile("cp.async.commit_group;\n");
}
template<int N>
__device__ __forceinline__ void cp_wait() {
    asm volatile("cp.async.wait_group %0;\n" :: "n"(N));
}

// ---------------------------------------------------------------------------
// FP16 tensor-core GEMM: C[M,N] = epi( A[M,K] @ W[N,K]^T + bias[N] [+res] )
// A, W fp16; accumulate fp32; epilogue fp32. CTA tile 128x128, BK=64,
// 4-stage cp.async ring, 512 thr = 16 warps (4x4, warp tile 32x32).
// Fragment double-buffering across the 4 k16-steps per iteration.
// Smem rows padded to 72 halves (144B): every 8-lane ldmatrix phase hits
// banks {4r..4r+3 mod 32} -> conflict-free (same geometry as round 10).
// Requires M%128==0, N%128==0, K%64==0.
// OUT16: write fp16 to C16 (feeds next GEMM); else fp32 to C32.
// ---------------------------------------------------------------------------
#define SROW_H       72                        // halves per padded row (144 B)
#define A_TILE_H     (128 * SROW_H)            // 9216 halves
#define STAGE_H      (2 * A_TILE_H)            // A + B
#define STAGE_BYTES  (STAGE_H * 2)             // 36864
#define GEMM_STAGES  4
#define GEMM_SMEM    (GEMM_STAGES * STAGE_BYTES)   // 147456 (144 KB)

template<int ACT, bool RES, bool OUT16>
__global__ __launch_bounds__(512, 1)
void hgemm_kernel(const __half* __restrict__ A,
                  const __half* __restrict__ W,
                  const float*  __restrict__ bias,
                  const float*  __restrict__ res,
                  float*        __restrict__ C32,
                  __half*       __restrict__ C16,
                  int M, int N, int K)
{
    extern __shared__ __half smh[];

    const int bm   = blockIdx.y * 128;
    const int bn   = blockIdx.x * 128;
    const int tid  = threadIdx.x;
    const int warp = tid >> 5;
    const int lane = tid & 31;
    const int wm   = (warp >> 2) * 32;   // 4 warp rows
    const int wn   = (warp & 3) * 32;    // 4 warp cols

    // ---- gmem -> smem: row r0 (0..127), 16-half chunk c0; 2x16B per operand ----
    const int r0 = tid >> 2;
    const int c0 = (tid & 3) * 16;       // halves within 64-half slab
    const __half* Ag = A + (size_t)(bm + r0) * K + c0;
    const __half* Wg = W + (size_t)(bn + r0) * K + c0;

    const uint32_t sbase = (uint32_t)__cvta_generic_to_shared((void*)smh);
    const uint32_t aoff  = (uint32_t)(r0 * SROW_H + c0) * 2;   // bytes
    const uint32_t boff  = (uint32_t)(A_TILE_H * 2) + aoff;

    // ---- ldmatrix per-lane addressing (canonical m16n8k16) ----
    const int arow = lane & 15;              // A: row within m16 tile
    const int acol = (lane >> 4) * 8;        // A: k-half offset
    const int brow = ((lane >> 4) << 3) + (lane & 7);   // B: n row within n16
    const int bcol = ((lane >> 3) & 1) * 8;             // B: k-half offset

    float acc[2][4][4];
    #pragma unroll
    for (int mt = 0; mt < 2; mt++)
        #pragma unroll
        for (int nt = 0; nt < 4; nt++)
            #pragma unroll
            for (int i = 0; i < 4; i++) acc[mt][nt][i] = 0.0f;

    const int nk = K >> 6;   // BK=64

    // ---- prologue: stages 0..2 in flight ----
    #pragma unroll
    for (int s = 0; s < GEMM_STAGES - 1; s++) {
        const __half* a = Ag + (size_t)s * 64;
        const __half* w = Wg + (size_t)s * 64;
        const uint32_t base = sbase + s * STAGE_BYTES;
        cp_async16(base + aoff,      a);
        cp_async16(base + aoff + 16, a + 8);
        cp_async16(base + boff,      w);
        cp_async16(base + boff + 16, w + 8);
        cp_commit();
    }

    int s_cur = 0, s_nxt = GEMM_STAGES - 1;
    for (int kt = 0; kt < nk; kt++) {
        cp_wait<GEMM_STAGES - 2>();
        __syncthreads();

        if (kt + GEMM_STAGES - 1 < nk) {
            const __half* a = Ag + (size_t)(kt + GEMM_STAGES - 1) * 64;
            const __half* w = Wg + (size_t)(kt + GEMM_STAGES - 1) * 64;
            const uint32_t base = sbase + s_nxt * STAGE_BYTES;
            cp_async16(base + aoff,      a);
            cp_async16(base + aoff + 16, a + 8);
            cp_async16(base + boff,      w);
            cp_async16(base + boff + 16, w + 8);
        }
        cp_commit();   // empty groups at the tail keep wait counts valid

        const __half* Ac = smh + s_cur * STAGE_H;
        const __half* Bc = Ac + A_TILE_H;

        // ---- 4 k16-steps, fragment double-buffered ----
        uint32_t afr[2][2][4];
        uint32_t bfr[2][4][2];

        // load ks=0 into buffer 0
        #pragma unroll
        for (int mt = 0; mt < 2; mt++)
            ldm_x4h(afr[0][mt], &Ac[(wm + mt * 16 + arow) * SROW_H + acol]);
        #pragma unroll
        for (int j = 0; j < 2; j++) {
            uint32_t t[4];
            ldm_x4h(t, &Bc[(wn + j * 16 + brow) * SROW_H + bcol]);
            bfr[0][2 * j][0]     = t[0];
            bfr[0][2 * j][1]     = t[1];
            bfr[0][2 * j + 1][0] = t[2];
            bfr[0][2 * j + 1][1] = t[3];
        }

        #pragma unroll
        for (int ks = 0; ks < 4; ks++) {
            const int cb = ks & 1;
            if (ks < 3) {
                const int nb = cb ^ 1;
                const int kc = (ks + 1) * 16;
                #pragma unroll
                for (int mt = 0; mt < 2; mt++)
                    ldm_x4h(afr[nb][mt], &Ac[(wm + mt * 16 + arow) * SROW_H + kc + acol]);
                #pragma unroll
                for (int j = 0; j < 2; j++) {
                    uint32_t t[4];
                    ldm_x4h(t, &Bc[(wn + j * 16 + brow) * SROW_H + kc + bcol]);
                    bfr[nb][2 * j][0]     = t[0];
                    bfr[nb][2 * j][1]     = t[1];
                    bfr[nb][2 * j + 1][0] = t[2];
                    bfr[nb][2 * j + 1][1] = t[3];
                }
            }
            #pragma unroll
            for (int mt = 0; mt < 2; mt++)
                #pragma unroll
                for (int nt = 0; nt < 4; nt++)
                    mma_f16(acc[mt][nt], afr[cb][mt], bfr[cb][nt]);
        }

        s_cur = (s_cur + 1 == GEMM_STAGES) ? 0 : s_cur + 1;
        s_nxt = (s_nxt + 1 == GEMM_STAGES) ? 0 : s_nxt + 1;
    }

    // ---- epilogue: bias (+gelu) (+res); fp32 or fp16 stores ----
    const int g  = lane >> 2;
    const int cc = (lane & 3) * 2;
    #pragma unroll
    for (int mt = 0; mt < 2; mt++) {
        const int row = bm + wm + mt * 16 + g;   // and row+8
        #pragma unroll
        for (int nt = 0; nt < 4; nt++) {
            const int col = bn + wn + nt * 8 + cc;
            const float2 bv = *(const float2*)&bias[col];
            float v0 = acc[mt][nt][0] + bv.x;
            float v1 = acc[mt][nt][1] + bv.y;
            float v2 = acc[mt][nt][2] + bv.x;
            float v3 = acc[mt][nt][3] + bv.y;
            if (ACT == 1) {
                v0 = gelu_exact(v0); v1 = gelu_exact(v1);
                v2 = gelu_exact(v2); v3 = gelu_exact(v3);
            }
            if (RES) {
                const float2 ra = *(const float2*)&res[(size_t)row * N + col];
                const float2 rb = *(const float2*)&res[(size_t)(row + 8) * N + col];
                v0 += ra.x; v1 += ra.y; v2 += rb.x; v3 += rb.y;
            }
            if (OUT16) {
                *(__half2*)&C16[(size_t)row * N + col]       = __floats2half2_rn(v0, v1);
                *(__half2*)&C16[(size_t)(row + 8) * N + col] = __floats2half2_rn(v2, v3);
            } else {
                float2 o0 = {v0, v1};
                float2 o1 = {v2, v3};
                *(float2*)&C32[(size_t)row * N + col]       = o0;
                *(float2*)&C32[(size_t)(row + 8) * N + col] = o1;
            }
        }
    }
}

// ---------------------------------------------------------------------------
// fp32 -> fp16 conversion (weights; half2-vectorized)
// ---------------------------------------------------------------------------
__global__ void cvt_kernel(const float* __restrict__ s, __half* __restrict__ d, int n2) {
    int i = blockIdx.x * blockDim.x + threadIdx.x;
    if (i < n2) {
        float2 v = ((const float2*)s)[i];
        ((__half2*)d)[i] = __floats2half2_rn(v.x, v.y);
    }
}

// ---------------------------------------------------------------------------
// LayerNorm over last dim (E=512), fp16 output (feeds GEMM A).
// Stats and normalization in fp32, round once at store.
// ---------------------------------------------------------------------------
__global__ void ln16_kernel(const float* __restrict__ x,
                            const float* __restrict__ g,
                            const float* __restrict__ b,
                            __half* __restrict__ y)
{
    const int row = blockIdx.x;
    const int t   = threadIdx.x;  // 0..127
    const float4 v = ((const float4*)(x + (size_t)row * EMB))[t];

    float s  = v.x + v.y + v.z + v.w;
    float ss = v.x * v.x + v.y * v.y + v.z * v.z + v.w * v.w;
    #pragma unroll
    for (int o = 16; o; o >>= 1) {
        s  += __shfl_xor_sync(0xffffffffu, s,  o);
        ss += __shfl_xor_sync(0xffffffffu, ss, o);
    }
    __shared__ float sm[4], sm2[4];
    if ((t & 31) == 0) { sm[t >> 5] = s; sm2[t >> 5] = ss; }
    __syncthreads();
    s  = sm[0]  + sm[1]  + sm[2]  + sm[3];
    ss = sm2[0] + sm2[1] + sm2[2] + sm2[3];

    const float mean = s * (1.0f / EMB);
    const float var  = ss * (1.0f / EMB) - mean * mean;
    const float inv  = rsqrtf(var + 1e-5f);

    const float4 gg = ((const float4*)g)[t];
    const float4 bb = ((const float4*)b)[t];
    const float ox = (v.x - mean) * inv * gg.x + bb.x;
    const float oy = (v.y - mean) * inv * gg.y + bb.y;
    const float oz = (v.z - mean) * inv * gg.z + bb.z;
    const float ow = (v.w - mean) * inv * gg.w + bb.w;

    __half2* yp = (__half2*)(y + (size_t)row * EMB);
    yp[2 * t]     = __floats2half2_rn(ox, oy);
    yp[2 * t + 1] = __floats2half2_rn(oz, ow);
}

// ---------------------------------------------------------------------------
// Windowed attention. One warp per (batch, head, query); <=9 unmasked keys.
// Reads fp32 qkv; all math fp32; writes fp16 (feeds out-proj GEMM).
// ---------------------------------------------------------------------------
__global__ void attn_kernel(const float* __restrict__ qkv,
                            __half* __restrict__ out)
{
    const int gw   = blockIdx.x * 8 + (threadIdx.x >> 5);
    const int lane = threadIdx.x & 31;

    const int qpos = gw & (SEQ - 1);
    const int h    = (gw >> 10) & (HEADS - 1);
    const int b    = gw >> 13;

    const int row = b * SEQ + qpos;
    const float* qp = qkv + (size_t)row * (3 * EMB) + h * HDIM;
    const float q0 = qp[lane]      * 0.125f;   // 1/sqrt(64)
    const float q1 = qp[lane + 32] * 0.125f;

    const int y = qpos >> 5;
    const int x = qpos & 31;

    float s[9];
    int   krow[9];
    int   n = 0;
    #pragma unroll
    for (int dy = -1; dy <= 1; dy++) {
        #pragma unroll
        for (int dx = -1; dx <= 1; dx++) {
            const int ny = y + dy, nx = x + dx;
            if (ny < 0 || ny >= GRID_W || nx < 0 || nx >= GRID_W) continue;
            const int kr = b * SEQ + (ny << 5) + nx;
            const float* kp = qkv + (size_t)kr * (3 * EMB) + EMB + h * HDIM;
            float p = q0 * kp[lane] + q1 * kp[lane + 32];
            #pragma unroll
            for (int o = 16; o; o >>= 1) p += __shfl_xor_sync(0xffffffffu, p, o);
            s[n] = p; krow[n] = kr; n++;
        }
    }

    float mx = s[0];
    for (int j = 1; j < n; j++) mx = fmaxf(mx, s[j]);
    float sum = 0.0f;
    for (int j = 0; j < n; j++) { s[j] = expf(s[j] - mx); sum += s[j]; }
    const float inv = 1.0f / sum;

    float o0 = 0.0f, o1 = 0.0f;
    for (int j = 0; j < n; j++) {
        const float* vp = qkv + (size_t)krow[j] * (3 * EMB) + 2 * EMB + h * HDIM;
        const float a = s[j] * inv;
        o0 = fmaf(a, vp[lane],      o0);
        o1 = fmaf(a, vp[lane + 32], o1);
    }
    __half* op = out + (size_t)row * EMB + h * HDIM;
    op[lane]      = __float2half_rn(o0);
    op[lane + 32] = __float2half_rn(o1);
}

// ---------------------------------------------------------------------------
// Elementwise helper
// ---------------------------------------------------------------------------
__global__ void add_kernel(const float* __restrict__ a, const float* __restrict__ b,
                           float* __restrict__ dst, int n4) {
    int i = blockIdx.x * blockDim.x + threadIdx.x;
    if (i < n4) {
        float4 va = ((const float4*)a)[i];
        float4 vb = ((const float4*)b)[i];
        float4 o = {va.x + vb.x, va.y + vb.y, va.z + vb.z, va.w + vb.w};
        ((float4*)dst)[i] = o;
    }
}

// ---------------------------------------------------------------------------
// Host orchestration
// ---------------------------------------------------------------------------
// mode 0: plain fp32 out; mode 1: +res, fp32 out; mode 2: gelu, fp16 out
static inline void run_h(int mode, const __half* A, const __half* W,
                         const float* bias, const float* res,
                         float* C32, __half* C16, int M, int N, int K,
                         cudaStream_t s)
{
    dim3 grid(N / 128, M / 128);
    if (mode == 0)
        hgemm_kernel<0, false, false><<<grid, 512, GEMM_SMEM, s>>>(A, W, bias, nullptr, C32, nullptr, M, N, K);
    else if (mode == 1)
        hgemm_kernel<0, true,  false><<<grid, 512, GEMM_SMEM, s>>>(A, W, bias, res, C32, nullptr, M, N, K);
    else
        hgemm_kernel<1, false, true ><<<grid, 512, GEMM_SMEM, s>>>(A, W, bias, nullptr, nullptr, C16, M, N, K);
}

extern "C" void kernel_launch(void* const* d_in, const int* in_sizes, int n_in,
                              void* d_out, int out_size)
{
    (void)in_sizes; (void)n_in; (void)out_size;
    const float* x      = (const float*)d_in[0];
    // d_in[1] = mask : structure exploited analytically (3x3 window, 32x32 grid)
    const float* in_w   = (const float*)d_in[2];
    const float* in_b   = (const float*)d_in[3];
    const float* out_w  = (const float*)d_in[4];
    const float* out_b  = (const float*)d_in[5];
    const float* ln1_g  = (const float*)d_in[6];
    const float* ln1_b  = (const float*)d_in[7];
    const float* ln2_g  = (const float*)d_in[8];
    const float* ln2_b  = (const float*)d_in[9];
    const float* ff1_w  = (const float*)d_in[10];
    const float* ff1_b  = (const float*)d_in[11];
    const float* ff2_w  = (const float*)d_in[12];
    const float* ff2_b  = (const float*)d_in[13];
    const float* mlp_ln_g = (const float*)d_in[14];
    const float* mlp_ln_b = (const float*)d_in[15];
    const float* mlp_w1 = (const float*)d_in[16];
    const float* mlp_b1 = (const float*)d_in[17];
    const float* mlp_w2 = (const float*)d_in[18];
    const float* mlp_b2 = (const float*)d_in[19];
    float* out = (float*)d_out;

    // opt-in to >48KB dynamic smem (host-side, idempotent, not captured)
    cudaFuncSetAttribute(hgemm_kernel<0, false, false>, cudaFuncAttributeMaxDynamicSharedMemorySize, GEMM_SMEM);
    cudaFuncSetAttribute(hgemm_kernel<0, true,  false>, cudaFuncAttributeMaxDynamicSharedMemorySize, GEMM_SMEM);
    cudaFuncSetAttribute(hgemm_kernel<1, false, true >, cudaFuncAttributeMaxDynamicSharedMemorySize, GEMM_SMEM);

    float *h, *qkv;
    __half *ln16, *att16, *ff16, *mid16;
    __half *inw16, *outw16, *ff1w16, *ff2w16, *mw1_16, *mw2_16;
    cudaGetSymbolAddress((void**)&h,      g_h);
    cudaGetSymbolAddress((void**)&qkv,    g_qkv);
    cudaGetSymbolAddress((void**)&ln16,   g_ln16);
    cudaGetSymbolAddress((void**)&att16,  g_att16);
    cudaGetSymbolAddress((void**)&ff16,   g_ff16);
    cudaGetSymbolAddress((void**)&mid16,  g_mid16);
    cudaGetSymbolAddress((void**)&inw16,  g_inw16);
    cudaGetSymbolAddress((void**)&outw16, g_outw16);
    cudaGetSymbolAddress((void**)&ff1w16, g_ff1w16);
    cudaGetSymbolAddress((void**)&ff2w16, g_ff2w16);
    cudaGetSymbolAddress((void**)&mw1_16, g_mw1_16);
    cudaGetSymbolAddress((void**)&mw2_16, g_mw2_16);

    cudaStream_t s = 0;
    const int M = MROWS, E = EMB;

    // ---- convert weights fp32 -> fp16 (graph-captured, deterministic) ----
    const int cb = 256;
    auto cvt = [&](const float* src, __half* dst, int n) {
        int n2 = n / 2;
        cvt_kernel<<<(n2 + cb - 1) / cb, cb, 0, s>>>(src, dst, n2);
    };
    cvt(in_w,   inw16,  LAYERS * 3 * E * E);
    cvt(out_w,  outw16, LAYERS * E * E);
    cvt(ff1_w,  ff1w16, LAYERS * E * E);
    cvt(ff2_w,  ff2w16, LAYERS * E * E);
    cvt(mlp_w1, mw1_16, 4 * E * E);
    cvt(mlp_w2, mw2_16, 4 * E * E);

    const int n4 = M * E / 4;
    const int eg = (n4 + cb - 1) / cb;

    const float* cur = x;   // residual stream; layer 0 reads the input directly

    for (int l = 0; l < LAYERS; l++) {
        const __half* iw  = inw16  + (size_t)l * 3 * E * E;
        const __half* ow  = outw16 + (size_t)l * E * E;
        const __half* f1w = ff1w16 + (size_t)l * E * E;
        const __half* f2w = ff2w16 + (size_t)l * E * E;
        const float*  ib  = in_b  + (size_t)l * 3 * E;
        const float*  ob  = out_b + (size_t)l * E;
        const float*  l1g = ln1_g + (size_t)l * E;
        const float*  l1b = ln1_b + (size_t)l * E;
        const float*  l2g = ln2_g + (size_t)l * E;
        const float*  l2b = ln2_b + (size_t)l * E;
        const float*  f1b = ff1_b + (size_t)l * E;
        const float*  f2b = ff2_b + (size_t)l * E;

        // ln16 = LN1(cur)            [fp16]
        ln16_kernel<<<M, 128, 0, s>>>(cur, l1g, l1b, ln16);
        // qkv = ln16 @ in_w^T + in_b [fp32]
        run_h(0, ln16, iw, ib, nullptr, qkv, nullptr, M, 3 * E, E, s);
        // att16 = windowed attention [fp16]
        attn_kernel<<<(BATCH * HEADS * SEQ) / 8, 256, 0, s>>>(qkv, att16);
        // h = cur + att16 @ out_w^T + out_b
        run_h(1, att16, ow, ob, cur, h, nullptr, M, E, E, s);
        cur = h;
        // ln16 = LN2(h)
        ln16_kernel<<<M, 128, 0, s>>>(h, l2g, l2b, ln16);
        // ff16 = gelu(ln16 @ ff1_w^T + ff1_b) [fp16]
        run_h(2, ln16, f1w, f1b, nullptr, nullptr, ff16, M, E, E, s);
        // h = h + ff16 @ ff2_w^T + ff2_b
        run_h(1, ff16, f2w, f2b, h, h, nullptr, M, E, E, s);
    }

    // out = x + h
    add_kernel<<<eg, cb, 0, s>>>(x, h, out, n4);
    // ln16 = LN(out)
    ln16_kernel<<<M, 128, 0, s>>>(out, mlp_ln_g, mlp_ln_b, ln16);
    // mid16 = gelu(ln16 @ mlp_w1^T + mlp_b1)   [M, 2048] fp16
    run_h(2, ln16, mw1_16, mlp_b1, nullptr, nullptr, mid16, M, 4 * E, E, s);
    // out = out + mid16 @ mlp_w2^T + mlp_b2
    run_h(1, mid16, mw2_16, mlp_b2, out, out, nullptr, M, E, 4 * E, s);
}

// round 12
// speedup vs baseline: 1.5584x; 1.0099x over previous
#include <cuda_runtime.h>
#include <cuda_fp16.h>
#include <math.h>
#include <stdint.h>

// ---------------------------------------------------------------------------
// Problem constants (fixed by setup_inputs)
// ---------------------------------------------------------------------------
#define BATCH   4
#define SEQ     1024          // 32*32 grid
#define EMB     512
#define HEADS   8
#define HDIM    64            // EMB / HEADS
#define LAYERS  4
#define MROWS   (BATCH * SEQ) // 4096
#define GRID_W  32            // sqrt(SEQ)

// ---------------------------------------------------------------------------
// Scratch (device globals; no allocation allowed)
// ---------------------------------------------------------------------------
__device__ float  g_h    [MROWS * EMB];          // residual stream (fp32)
__device__ __half g_qkv16[MROWS * 3 * EMB];      // QKV (fp16: attention operands)
__device__ __half g_ln16 [MROWS * EMB];          // LN output (fp16 GEMM A)
__device__ __half g_att16[MROWS * EMB];          // attention output (fp16 GEMM A)
__device__ __half g_ff16 [MROWS * EMB];          // FF1 output (fp16 GEMM A)
__device__ __half g_mid16[MROWS * 4 * EMB];      // final-MLP hidden (fp16 GEMM A)
// fp16 weight mirrors (converted per launch)
__device__ __half g_inw16 [LAYERS * 3 * EMB * EMB];
__device__ __half g_outw16[LAYERS * EMB * EMB];
__device__ __half g_ff1w16[LAYERS * EMB * EMB];
__device__ __half g_ff2w16[LAYERS * EMB * EMB];
__device__ __half g_mw1_16[4 * EMB * EMB];
__device__ __half g_mw2_16[4 * EMB * EMB];

// ---------------------------------------------------------------------------
// GELU (exact, erf-based — matches jax.nn.gelu(approximate=False))
// ---------------------------------------------------------------------------
__device__ __forceinline__ float gelu_exact(float x) {
    return 0.5f * x * (1.0f + erff(x * 0.70710678118654752440f));
}

// ---------------------------------------------------------------------------
// Tensor-core primitives (FP16 m16n8k16, fp32 accumulate).
// mma asm non-volatile: register-only op, data deps enforce correctness.
// ---------------------------------------------------------------------------
__device__ __forceinline__ void mma_f16(float* d, const uint32_t* a, const uint32_t* b) {
    asm("mma.sync.aligned.m16n8k16.row.col.f32.f16.f16.f32 "
        "{%0,%1,%2,%3}, {%4,%5,%6,%7}, {%8,%9}, {%0,%1,%2,%3};\n"
        : "+f"(d[0]), "+f"(d[1]), "+f"(d[2]), "+f"(d[3])
        : "r"(a[0]), "r"(a[1]), "r"(a[2]), "r"(a[3]), "r"(b[0]), "r"(b[1]));
}

__device__ __forceinline__ void ldm_x4h(uint32_t* f, const __half* p) {
    uint32_t s = (uint32_t)__cvta_generic_to_shared((void*)p);
    asm volatile("ldmatrix.sync.aligned.m8n8.x4.shared.b16 {%0,%1,%2,%3}, [%4];\n"
        : "=r"(f[0]), "=r"(f[1]), "=r"(f[2]), "=r"(f[3]) : "r"(s));
}

__device__ __forceinline__ void cp_async16(uint32_t saddr, const void* gptr) {
    asm volatile("cp.async.cg.shared.global [%0], [%1], 16;\n" :: "r"(saddr), "l"(gptr));
}
__device__ __forceinline__ void cp_commit() {
    asm volatile("cp.async.commit_group;\n");
}
template<int N>
__device__ __forceinline__ void cp_wait() {
    asm volatile("cp.async.wait_group %0;\n" :: "n"(N));
}

// ---------------------------------------------------------------------------
// FP16 tensor-core GEMM: C[M,N] = epi( A[M,K] @ W[N,K]^T + bias[N] [+res] )
// A, W fp16; accumulate fp32; epilogue fp32. CTA tile 128x128, BK=64,
// 4-stage cp.async ring, 512 thr = 16 warps (4x4, warp tile 32x32).
// Fragment double-buffering across the 4 k16-steps per iteration.
// Smem rows padded to 72 halves (144B): conflict-free ldmatrix phases.
// Requires M%128==0, N%128==0, K%64==0.
// ---------------------------------------------------------------------------
#define SROW_H       72                        // halves per padded row (144 B)
#define A_TILE_H     (128 * SROW_H)            // 9216 halves
#define STAGE_H      (2 * A_TILE_H)            // A + B
#define STAGE_BYTES  (STAGE_H * 2)             // 36864
#define GEMM_STAGES  4
#define GEMM_SMEM    (GEMM_STAGES * STAGE_BYTES)   // 147456 (144 KB)

template<int ACT, bool RES, bool OUT16>
__global__ __launch_bounds__(512, 1)
void hgemm_kernel(const __half* __restrict__ A,
                  const __half* __restrict__ W,
                  const float*  __restrict__ bias,
                  const float*  __restrict__ res,
                  float*        __restrict__ C32,
                  __half*       __restrict__ C16,
                  int M, int N, int K)
{
    extern __shared__ __half smh[];

    const int bm   = blockIdx.y * 128;
    const int bn   = blockIdx.x * 128;
    const int tid  = threadIdx.x;
    const int warp = tid >> 5;
    const int lane = tid & 31;
    const int wm   = (warp >> 2) * 32;   // 4 warp rows
    const int wn   = (warp & 3) * 32;    // 4 warp cols

    // ---- gmem -> smem: row r0 (0..127), 16-half chunk c0; 2x16B per operand ----
    const int r0 = tid >> 2;
    const int c0 = (tid & 3) * 16;       // halves within 64-half slab
    const __half* Ag = A + (size_t)(bm + r0) * K + c0;
    const __half* Wg = W + (size_t)(bn + r0) * K + c0;

    const uint32_t sbase = (uint32_t)__cvta_generic_to_shared((void*)smh);
    const uint32_t aoff  = (uint32_t)(r0 * SROW_H + c0) * 2;   // bytes
    const uint32_t boff  = (uint32_t)(A_TILE_H * 2) + aoff;

    // ---- ldmatrix per-lane addressing (canonical m16n8k16) ----
    const int arow = lane & 15;              // A: row within m16 tile
    const int acol = (lane >> 4) * 8;        // A: k-half offset
    const int brow = ((lane >> 4) << 3) + (lane & 7);   // B: n row within n16
    const int bcol = ((lane >> 3) & 1) * 8;             // B: k-half offset

    float acc[2][4][4];
    #pragma unroll
    for (int mt = 0; mt < 2; mt++)
        #pragma unroll
        for (int nt = 0; nt < 4; nt++)
            #pragma unroll
            for (int i = 0; i < 4; i++) acc[mt][nt][i] = 0.0f;

    const int nk = K >> 6;   // BK=64

    // ---- prologue: stages 0..2 in flight ----
    #pragma unroll
    for (int s = 0; s < GEMM_STAGES - 1; s++) {
        const __half* a = Ag + (size_t)s * 64;
        const __half* w = Wg + (size_t)s * 64;
        const uint32_t base = sbase + s * STAGE_BYTES;
        cp_async16(base + aoff,      a);
        cp_async16(base + aoff + 16, a + 8);
        cp_async16(base + boff,      w);
        cp_async16(base + boff + 16, w + 8);
        cp_commit();
    }

    int s_cur = 0, s_nxt = GEMM_STAGES - 1;
    for (int kt = 0; kt < nk; kt++) {
        cp_wait<GEMM_STAGES - 2>();
        __syncthreads();

        if (kt + GEMM_STAGES - 1 < nk) {
            const __half* a = Ag + (size_t)(kt + GEMM_STAGES - 1) * 64;
            const __half* w = Wg + (size_t)(kt + GEMM_STAGES - 1) * 64;
            const uint32_t base = sbase + s_nxt * STAGE_BYTES;
            cp_async16(base + aoff,      a);
            cp_async16(base + aoff + 16, a + 8);
            cp_async16(base + boff,      w);
            cp_async16(base + boff + 16, w + 8);
        }
        cp_commit();   // empty groups at the tail keep wait counts valid

        const __half* Ac = smh + s_cur * STAGE_H;
        const __half* Bc = Ac + A_TILE_H;

        // ---- 4 k16-steps, fragment double-buffered ----
        uint32_t afr[2][2][4];
        uint32_t bfr[2][4][2];

        #pragma unroll
        for (int mt = 0; mt < 2; mt++)
            ldm_x4h(afr[0][mt], &Ac[(wm + mt * 16 + arow) * SROW_H + acol]);
        #pragma unroll
        for (int j = 0; j < 2; j++) {
            uint32_t t[4];
            ldm_x4h(t, &Bc[(wn + j * 16 + brow) * SROW_H + bcol]);
            bfr[0][2 * j][0]     = t[0];
            bfr[0][2 * j][1]     = t[1];
            bfr[0][2 * j + 1][0] = t[2];
            bfr[0][2 * j + 1][1] = t[3];
        }

        #pragma unroll
        for (int ks = 0; ks < 4; ks++) {
            const int cb = ks & 1;
            if (ks < 3) {
                const int nb = cb ^ 1;
                const int kc = (ks + 1) * 16;
                #pragma unroll
                for (int mt = 0; mt < 2; mt++)
                    ldm_x4h(afr[nb][mt], &Ac[(wm + mt * 16 + arow) * SROW_H + kc + acol]);
                #pragma unroll
                for (int j = 0; j < 2; j++) {
                    uint32_t t[4];
                    ldm_x4h(t, &Bc[(wn + j * 16 + brow) * SROW_H + kc + bcol]);
                    bfr[nb][2 * j][0]     = t[0];
                    bfr[nb][2 * j][1]     = t[1];
                    bfr[nb][2 * j + 1][0] = t[2];
                    bfr[nb][2 * j + 1][1] = t[3];
                }
            }
            #pragma unroll
            for (int mt = 0; mt < 2; mt++)
                #pragma unroll
                for (int nt = 0; nt < 4; nt++)
                    mma_f16(acc[mt][nt], afr[cb][mt], bfr[cb][nt]);
        }

        s_cur = (s_cur + 1 == GEMM_STAGES) ? 0 : s_cur + 1;
        s_nxt = (s_nxt + 1 == GEMM_STAGES) ? 0 : s_nxt + 1;
    }

    // ---- epilogue: bias (+gelu) (+res); fp32 or fp16 stores ----
    const int g  = lane >> 2;
    const int cc = (lane & 3) * 2;
    #pragma unroll
    for (int mt = 0; mt < 2; mt++) {
        const int row = bm + wm + mt * 16 + g;   // and row+8
        #pragma unroll
        for (int nt = 0; nt < 4; nt++) {
            const int col = bn + wn + nt * 8 + cc;
            const float2 bv = *(const float2*)&bias[col];
            float v0 = acc[mt][nt][0] + bv.x;
            float v1 = acc[mt][nt][1] + bv.y;
            float v2 = acc[mt][nt][2] + bv.x;
            float v3 = acc[mt][nt][3] + bv.y;
            if (ACT == 1) {
                v0 = gelu_exact(v0); v1 = gelu_exact(v1);
                v2 = gelu_exact(v2); v3 = gelu_exact(v3);
            }
            if (RES) {
                const float2 ra = *(const float2*)&res[(size_t)row * N + col];
                const float2 rb = *(const float2*)&res[(size_t)(row + 8) * N + col];
                v0 += ra.x; v1 += ra.y; v2 += rb.x; v3 += rb.y;
            }
            if (OUT16) {
                *(__half2*)&C16[(size_t)row * N + col]       = __floats2half2_rn(v0, v1);
                *(__half2*)&C16[(size_t)(row + 8) * N + col] = __floats2half2_rn(v2, v3);
            } else {
                float2 o0 = {v0, v1};
                float2 o1 = {v2, v3};
                *(float2*)&C32[(size_t)row * N + col]       = o0;
                *(float2*)&C32[(size_t)(row + 8) * N + col] = o1;
            }
        }
    }
}

// ---------------------------------------------------------------------------
// fp32 -> fp16 conversion (weights; half2-vectorized)
// ---------------------------------------------------------------------------
__global__ void cvt_kernel(const float* __restrict__ s, __half* __restrict__ d, int n2) {
    int i = blockIdx.x * blockDim.x + threadIdx.x;
    if (i < n2) {
        float2 v = ((const float2*)s)[i];
        ((__half2*)d)[i] = __floats2half2_rn(v.x, v.y);
    }
}

// ---------------------------------------------------------------------------
// LayerNorm over last dim (E=512), fp16 output (feeds GEMM A).
// Stats and normalization in fp32, round once at store.
// ---------------------------------------------------------------------------
__global__ void ln16_kernel(const float* __restrict__ x,
                            const float* __restrict__ g,
                            const float* __restrict__ b,
                            __half* __restrict__ y)
{
    const int row = blockIdx.x;
    const int t   = threadIdx.x;  // 0..127
    const float4 v = ((const float4*)(x + (size_t)row * EMB))[t];

    float s  = v.x + v.y + v.z + v.w;
    float ss = v.x * v.x + v.y * v.y + v.z * v.z + v.w * v.w;
    #pragma unroll
    for (int o = 16; o; o >>= 1) {
        s  += __shfl_xor_sync(0xffffffffu, s,  o);
        ss += __shfl_xor_sync(0xffffffffu, ss, o);
    }
    __shared__ float sm[4], sm2[4];
    if ((t & 31) == 0) { sm[t >> 5] = s; sm2[t >> 5] = ss; }
    __syncthreads();
    s  = sm[0]  + sm[1]  + sm[2]  + sm[3];
    ss = sm2[0] + sm2[1] + sm2[2] + sm2[3];

    const float mean = s * (1.0f / EMB);
    const float var  = ss * (1.0f / EMB) - mean * mean;
    const float inv  = rsqrtf(var + 1e-5f);

    const float4 gg = ((const float4*)g)[t];
    const float4 bb = ((const float4*)b)[t];
    const float ox = (v.x - mean) * inv * gg.x + bb.x;
    const float oy = (v.y - mean) * inv * gg.y + bb.y;
    const float oz = (v.z - mean) * inv * gg.z + bb.z;
    const float ow = (v.w - mean) * inv * gg.w + bb.w;

    __half2* yp = (__half2*)(y + (size_t)row * EMB);
    yp[2 * t]     = __floats2half2_rn(ox, oy);
    yp[2 * t + 1] = __floats2half2_rn(oz, ow);
}

// ---------------------------------------------------------------------------
// Windowed attention, fp16 operands / fp32 math. One warp per (b, head, q);
// <=9 unmasked keys (3x3 window on 32x32 grid == the additive -inf mask).
// Each head row is 64 halves = 128B = exactly one half2 per lane -> one L1
// wavefront per q/k/v row (round-11 profile: fp32 loads made attention
// L1-wavefront-bound at 63%).
// Lane-to-element permutation inside the dot product is reduction-invariant.
// ---------------------------------------------------------------------------
__global__ void attn_kernel(const __half* __restrict__ qkv,
                            __half* __restrict__ out)
{
    const int gw   = blockIdx.x * 8 + (threadIdx.x >> 5);
    const int lane = threadIdx.x & 31;

    const int qpos = gw & (SEQ - 1);
    const int h    = (gw >> 10) & (HEADS - 1);
    const int b    = gw >> 13;

    const int row = b * SEQ + qpos;
    const __half2* qp = (const __half2*)(qkv + (size_t)row * (3 * EMB) + h * HDIM);
    const float2 qv = __half22float2(qp[lane]);
    const float q0 = qv.x * 0.125f;   // 1/sqrt(64)
    const float q1 = qv.y * 0.125f;

    const int y = qpos >> 5;
    const int x = qpos & 31;

    float s[9];
    int   krow[9];
    int   n = 0;
    #pragma unroll
    for (int dy = -1; dy <= 1; dy++) {
        #pragma unroll
        for (int dx = -1; dx <= 1; dx++) {
            const int ny = y + dy, nx = x + dx;
            if (ny < 0 || ny >= GRID_W || nx < 0 || nx >= GRID_W) continue;
            const int kr = b * SEQ + (ny << 5) + nx;
            const __half2* kp = (const __half2*)(qkv + (size_t)kr * (3 * EMB) + EMB + h * HDIM);
            const float2 kv = __half22float2(kp[lane]);
            float p = fmaf(q0, kv.x, q1 * kv.y);
            #pragma unroll
            for (int o = 16; o; o >>= 1) p += __shfl_xor_sync(0xffffffffu, p, o);
            s[n] = p; krow[n] = kr; n++;
        }
    }

    float mx = s[0];
    for (int j = 1; j < n; j++) mx = fmaxf(mx, s[j]);
    float sum = 0.0f;
    for (int j = 0; j < n; j++) { s[j] = expf(s[j] - mx); sum += s[j]; }
    const float inv = 1.0f / sum;

    float o0 = 0.0f, o1 = 0.0f;
    for (int j = 0; j < n; j++) {
        const __half2* vp = (const __half2*)(qkv + (size_t)krow[j] * (3 * EMB) + 2 * EMB + h * HDIM);
        const float2 vv = __half22float2(vp[lane]);
        const float a = s[j] * inv;
        o0 = fmaf(a, vv.x, o0);
        o1 = fmaf(a, vv.y, o1);
    }
    ((__half2*)(out + (size_t)row * EMB + h * HDIM))[lane] = __floats2half2_rn(o0, o1);
}

// ---------------------------------------------------------------------------
// Elementwise helper
// ---------------------------------------------------------------------------
__global__ void add_kernel(const float* __restrict__ a, const float* __restrict__ b,
                           float* __restrict__ dst, int n4) {
    int i = blockIdx.x * blockDim.x + threadIdx.x;
    if (i < n4) {
        float4 va = ((const float4*)a)[i];
        float4 vb = ((const float4*)b)[i];
        float4 o = {va.x + vb.x, va.y + vb.y, va.z + vb.z, va.w + vb.w};
        ((float4*)dst)[i] = o;
    }
}

// ---------------------------------------------------------------------------
// Host orchestration
// ---------------------------------------------------------------------------
// mode 0: fp16 out (no act)     — QKV
// mode 1: +res, fp32 out        — out-proj / ff2 / mlp2
// mode 2: gelu, fp16 out        — ff1 / mlp1
static inline void run_h(int mode, const __half* A, const __half* W,
                         const float* bias, const float* res,
                         float* C32, __half* C16, int M, int N, int K,
                         cudaStream_t s)
{
    dim3 grid(N / 128, M / 128);
    if (mode == 0)
        hgemm_kernel<0, false, true ><<<grid, 512, GEMM_SMEM, s>>>(A, W, bias, nullptr, nullptr, C16, M, N, K);
    else if (mode == 1)
        hgemm_kernel<0, true,  false><<<grid, 512, GEMM_SMEM, s>>>(A, W, bias, res, C32, nullptr, M, N, K);
    else
        hgemm_kernel<1, false, true ><<<grid, 512, GEMM_SMEM, s>>>(A, W, bias, nullptr, nullptr, C16, M, N, K);
}

extern "C" void kernel_launch(void* const* d_in, const int* in_sizes, int n_in,
                              void* d_out, int out_size)
{
    (void)in_sizes; (void)n_in; (void)out_size;
    const float* x      = (const float*)d_in[0];
    // d_in[1] = mask : structure exploited analytically (3x3 window, 32x32 grid)
    const float* in_w   = (const float*)d_in[2];
    const float* in_b   = (const float*)d_in[3];
    const float* out_w  = (const float*)d_in[4];
    const float* out_b  = (const float*)d_in[5];
    const float* ln1_g  = (const float*)d_in[6];
    const float* ln1_b  = (const float*)d_in[7];
    const float* ln2_g  = (const float*)d_in[8];
    const float* ln2_b  = (const float*)d_in[9];
    const float* ff1_w  = (const float*)d_in[10];
    const float* ff1_b  = (const float*)d_in[11];
    const float* ff2_w  = (const float*)d_in[12];
    const float* ff2_b  = (const float*)d_in[13];
    const float* mlp_ln_g = (const float*)d_in[14];
    const float* mlp_ln_b = (const float*)d_in[15];
    const float* mlp_w1 = (const float*)d_in[16];
    const float* mlp_b1 = (const float*)d_in[17];
    const float* mlp_w2 = (const float*)d_in[18];
    const float* mlp_b2 = (const float*)d_in[19];
    float* out = (float*)d_out;

    // opt-in to >48KB dynamic smem (host-side, idempotent, not captured)
    cudaFuncSetAttribute(hgemm_kernel<0, false, true >, cudaFuncAttributeMaxDynamicSharedMemorySize, GEMM_SMEM);
    cudaFuncSetAttribute(hgemm_kernel<0, true,  false>, cudaFuncAttributeMaxDynamicSharedMemorySize, GEMM_SMEM);
    cudaFuncSetAttribute(hgemm_kernel<1, false, true >, cudaFuncAttributeMaxDynamicSharedMemorySize, GEMM_SMEM);

    float *h;
    __half *qkv16, *ln16, *att16, *ff16, *mid16;
    __half *inw16, *outw16, *ff1w16, *ff2w16, *mw1_16, *mw2_16;
    cudaGetSymbolAddress((void**)&h,      g_h);
    cudaGetSymbolAddress((void**)&qkv16,  g_qkv16);
    cudaGetSymbolAddress((void**)&ln16,   g_ln16);
    cudaGetSymbolAddress((void**)&att16,  g_att16);
    cudaGetSymbolAddress((void**)&ff16,   g_ff16);
    cudaGetSymbolAddress((void**)&mid16,  g_mid16);
    cudaGetSymbolAddress((void**)&inw16,  g_inw16);
    cudaGetSymbolAddress((void**)&outw16, g_outw16);
    cudaGetSymbolAddress((void**)&ff1w16, g_ff1w16);
    cudaGetSymbolAddress((void**)&ff2w16, g_ff2w16);
    cudaGetSymbolAddress((void**)&mw1_16, g_mw1_16);
    cudaGetSymbolAddress((void**)&mw2_16, g_mw2_16);

    cudaStream_t s = 0;
    const int M = MROWS, E = EMB;

    // ---- convert weights fp32 -> fp16 (graph-captured, deterministic) ----
    const int cb = 256;
    auto cvt = [&](const float* src, __half* dst, int n) {
        int n2 = n / 2;
        cvt_kernel<<<(n2 + cb - 1) / cb, cb, 0, s>>>(src, dst, n2);
    };
    cvt(in_w,   inw16,  LAYERS * 3 * E * E);
    cvt(out_w,  outw16, LAYERS * E * E);
    cvt(ff1_w,  ff1w16, LAYERS * E * E);
    cvt(ff2_w,  ff2w16, LAYERS * E * E);
    cvt(mlp_w1, mw1_16, 4 * E * E);
    cvt(mlp_w2, mw2_16, 4 * E * E);

    const int n4 = M * E / 4;
    const int eg = (n4 + cb - 1) / cb;

    const float* cur = x;   // residual stream; layer 0 reads the input directly

    for (int l = 0; l < LAYERS; l++) {
        const __half* iw  = inw16  + (size_t)l * 3 * E * E;
        const __half* ow  = outw16 + (size_t)l * E * E;
        const __half* f1w = ff1w16 + (size_t)l * E * E;
        const __half* f2w = ff2w16 + (size_t)l * E * E;
        const float*  ib  = in_b  + (size_t)l * 3 * E;
        const float*  ob  = out_b + (size_t)l * E;
        const float*  l1g = ln1_g + (size_t)l * E;
        const float*  l1b = ln1_b + (size_t)l * E;
        const float*  l2g = ln2_g + (size_t)l * E;
        const float*  l2b = ln2_b + (size_t)l * E;
        const float*  f1b = ff1_b + (size_t)l * E;
        const float*  f2b = ff2_b + (size_t)l * E;

        // ln16 = LN1(cur)                 [fp16]
        ln16_kernel<<<M, 128, 0, s>>>(cur, l1g, l1b, ln16);
        // qkv16 = ln16 @ in_w^T + in_b    [fp16]
        run_h(0, ln16, iw, ib, nullptr, nullptr, qkv16, M, 3 * E, E, s);
        // att16 = windowed attention      [fp16]
        attn_kernel<<<(BATCH * HEADS * SEQ) / 8, 256, 0, s>>>(qkv16, att16);
        // h = cur + att16 @ out_w^T + out_b
        run_h(1, att16, ow, ob, cur, h, nullptr, M, E, E, s);
        cur = h;
        // ln16 = LN2(h)
        ln16_kernel<<<M, 128, 0, s>>>(h, l2g, l2b, ln16);
        // ff16 = gelu(ln16 @ ff1_w^T + ff1_b) [fp16]
        run_h(2, ln16, f1w, f1b, nullptr, nullptr, ff16, M, E, E, s);
        // h = h + ff16 @ ff2_w^T + ff2_b
        run_h(1, ff16, f2w, f2b, h, h, nullptr, M, E, E, s);
    }

    // out = x + h
    add_kernel<<<eg, cb, 0, s>>>(x, h, out, n4);
    // ln16 = LN(out)
    ln16_kernel<<<M, 128, 0, s>>>(out, mlp_ln_g, mlp_ln_b, ln16);
    // mid16 = gelu(ln16 @ mlp_w1^T + mlp_b1)   [M, 2048] fp16
    run_h(2, ln16, mw1_16, mlp_b1, nullptr, nullptr, mid16, M, 4 * E, E, s);
    // out = out + mid16 @ mlp_w2^T + mlp_b2
    run_h(1, mid16, mw2_16, mlp_b2, out, out, nullptr, M, E, 4 * E, s);
}